// round 2
// baseline (speedup 1.0000x reference)
#include <cuda_runtime.h>
#include <math.h>

#define BS 2
#define NPTS 8192
#define C3D 64
#define HH 64
#define WW 160
#define HW (HH*WW)
#define KNN 3

#define FLT_BIG 3.402823466e+38f

// ---------------- scratch (static device arrays; no allocation) ----------------
__device__ float4 g_pts[BS * NPTS];              // (px, py, 0.5*(px^2+py^2), 0)
__device__ float  g_f3dT[BS * NPTS * C3D];       // point-major transpose of feat_3d
__device__ int4   g_knn[BS * HW];                // top-3 indices per query

// ---------------- prep: pack points + transpose feat_3d ----------------
__global__ void __launch_bounds__(256) prep_kernel(const float* __restrict__ uv,
                                                   const float* __restrict__ f3d) {
    int tid = blockIdx.x * blockDim.x + threadIdx.x;
    int stride = gridDim.x * blockDim.x;
    for (int i = tid; i < BS * NPTS; i += stride) {
        int b = i >> 13;          // /NPTS
        int n = i & (NPTS - 1);
        float ux = uv[(b * 2 + 0) * NPTS + n];
        float uy = uv[(b * 2 + 1) * NPTS + n];
        g_pts[i] = make_float4(ux, uy, 0.5f * (ux * ux + uy * uy), 0.0f);
    }
    for (int i = tid; i < BS * NPTS * C3D; i += stride) {
        int c = i & 63;
        int n = (i >> 6) & (NPTS - 1);
        int b = i >> 19;
        g_f3dT[i] = f3d[(b * C3D + c) * NPTS + n];
    }
}

// ---------------- KNN: 64 queries/block, 4-way point split ------
// Stage 1: fast surrogate metric, top-4 per 2048-point chunk.
// Stage 2: re-rank 16 candidates with bit-replica of the reference d2.
__device__ __forceinline__ bool lessMI(float ma, int ia, float mb, int ib) {
    return (ma < mb) || (ma == mb && ia < ib);
}

__global__ void __launch_bounds__(256) knn_kernel() {
    const int b     = blockIdx.y;
    const int q0    = blockIdx.x * 64;
    const int warp  = threadIdx.x >> 5;
    const int lane  = threadIdx.x & 31;
    const int qg    = warp & 1;    // query half (0..1)
    const int chunk = warp >> 1;   // point chunk (0..3)
    const int qi    = qg * 32 + lane;  // 0..63 local query
    const int q     = q0 + qi;

    const float qx = (float)(q % WW);
    const float qy = (float)(q / WW);

    const int CH = NPTS / 4;
    const int base = chunk * CH;
    const float4* __restrict__ pts = g_pts + b * NPTS + base;

    float m0 = FLT_BIG, m1 = FLT_BIG, m2 = FLT_BIG, m3 = FLT_BIG;
    int   i0 = 0x7fffffff, i1 = 0x7fffffff, i2 = 0x7fffffff, i3 = 0x7fffffff;

    #pragma unroll 4
    for (int j = 0; j < CH; ++j) {
        float4 p = __ldg(&pts[j]);
        float m = fmaf(-qy, p.y, p.z);
        m = fmaf(-qx, p.x, m);
        if (m < m3) {
            int idx = base + j;
            if (m < m1) {
                m3 = m2; i3 = i2; m2 = m1; i2 = i1;
                if (m < m0) { m1 = m0; i1 = i0; m0 = m; i0 = idx; }
                else        { m1 = m;  i1 = idx; }
            } else {
                if (m < m2) { m3 = m2; i3 = i2; m2 = m; i2 = idx; }
                else        { m3 = m;  i3 = idx; }
            }
        }
    }

    __shared__ int si[64 * 16];
    int o = qi * 16 + chunk * 4;
    si[o] = i0; si[o + 1] = i1; si[o + 2] = i2; si[o + 3] = i3;
    __syncthreads();

    if (threadIdx.x < 64) {
        const int qq = threadIdx.x;
        const int gq = q0 + qq;
        const float cqx = (float)(gq % WW);
        const float cqy = (float)(gq / WW);
        // s1 = gx*gx + gy*gy : exact integers in fp32
        const float s1 = __fadd_rn(__fmul_rn(cqx, cqx), __fmul_rn(cqy, cqy));

        float b0 = FLT_BIG, b1v = FLT_BIG, b2v = FLT_BIG;
        int   j0 = 0x7fffffff, j1 = 0x7fffffff, j2 = 0x7fffffff;
        #pragma unroll
        for (int t = 0; t < 16; ++t) {
            const int id = si[qq * 16 + t];
            const float4 p = __ldg(&g_pts[b * NPTS + id]);
            // replica of reference rounding:
            //   s2  = RN(RN(ux*ux) + RN(uy*uy))
            //   dot = fma(gy, uy, RN(gx*ux))        (GEMM K=2 accumulation)
            //   d2  = RN(RN(s1 + s2) - 2*dot)       (2*dot is exact)
            const float s2  = __fadd_rn(__fmul_rn(p.x, p.x), __fmul_rn(p.y, p.y));
            const float dot = __fmaf_rn(cqy, p.y, __fmul_rn(cqx, p.x));
            const float d2  = __fsub_rn(__fadd_rn(s1, s2), __fmul_rn(2.0f, dot));
            if (lessMI(d2, id, b2v, j2)) {
                if (lessMI(d2, id, b1v, j1)) {
                    b2v = b1v; j2 = j1;
                    if (lessMI(d2, id, b0, j0)) { b1v = b0; j1 = j0; b0 = d2; j0 = id; }
                    else                        { b1v = d2; j1 = id; }
                } else { b2v = d2; j2 = id; }
            }
        }
        g_knn[b * HW + gq] = make_int4(j0, j1, j2, 0);
    }
}

// ---------------- phase 2: gather + MLP + score + w3 GEMM ----------------
__global__ void __launch_bounds__(256) interp_kernel(
    const float* __restrict__ w1, const float* __restrict__ b1,
    const float* __restrict__ w2, const float* __restrict__ b2,
    const float* __restrict__ w3, const float* __restrict__ b3,
    float* __restrict__ out) {

    __shared__ float s_w3[64 * 65];    // s_w3[j*65 + o] = w3[o][j]
    __shared__ float s_fin[8][64];

    const int lane = threadIdx.x & 31;
    const int wib  = threadIdx.x >> 5;
    const int gw   = (blockIdx.x * blockDim.x + threadIdx.x) >> 5;  // 0..2559

    // cooperative w3 transpose into smem (reads coalesced)
    for (int e = threadIdx.x; e < 64 * 64; e += 256) {
        int o = e >> 6, j = e & 63;
        s_w3[j * 65 + o] = w3[e];
    }

    // per-lane persistent weights
    float w1a = 0.f, w1b = 0.f, w1c = 0.f, b1v = 0.f;
    if (lane < 16) {
        w1a = w1[lane * 3 + 0];
        w1b = w1[lane * 3 + 1];
        w1c = w1[lane * 3 + 2];
        b1v = b1[lane];
    }
    float w2r0[16], w2r1[16];
    #pragma unroll
    for (int j = 0; j < 16; ++j) {
        w2r0[j] = w2[lane * 16 + j];
        w2r1[j] = w2[(lane + 32) * 16 + j];
    }
    const float b2a = b2[lane],  b2b = b2[lane + 32];
    const float b3a = b3[lane],  b3b = b3[lane + 32];
    __syncthreads();

    for (int qq = 0; qq < 8; ++qq) {
        const int gq = gw * 8 + qq;          // 0..20479
        const int b  = gq / HW;
        const int q  = gq - b * HW;
        const float qx = (float)(q % WW);
        const float qy = (float)(q / WW);

        const int4 kn = g_knn[gq];

        float acc0 = 0.f, acc1 = 0.f;
        #pragma unroll
        for (int k = 0; k < KNN; ++k) {
            const int idx = (k == 0) ? kn.x : (k == 1) ? kn.y : kn.z;
            const float4 p = __ldg(&g_pts[b * NPTS + idx]);
            const float ox = p.x - qx;
            const float oy = p.y - qy;
            const float nr = sqrtf(ox * ox + oy * oy);
            // h1 (valid on lanes 0..15), broadcast via shfl
            float h = fmaf(w1a, ox, fmaf(w1b, oy, fmaf(w1c, nr, b1v)));
            h = fmaxf(h, 0.f);
            float d0 = b2a, d1 = b2b;
            #pragma unroll
            for (int j = 0; j < 16; ++j) {
                float hj = __shfl_sync(0xffffffffu, h, j);
                d0 = fmaf(w2r0[j], hj, d0);
                d1 = fmaf(w2r1[j], hj, d1);
            }
            const float s0 = 1.f / (1.f + __expf(-d0));
            const float s1 = 1.f / (1.f + __expf(-d1));
            const float* fp = g_f3dT + (size_t)(b * NPTS + idx) * C3D;
            acc0 = fmaf(s0, __ldg(fp + lane),      acc0);
            acc1 = fmaf(s1, __ldg(fp + lane + 32), acc1);
        }

        s_fin[wib][lane]      = acc0;
        s_fin[wib][lane + 32] = acc1;
        __syncwarp();

        float r0 = b3a, r1 = b3b;
        #pragma unroll 8
        for (int j = 0; j < 64; ++j) {
            float fj = s_fin[wib][j];
            r0 = fmaf(s_w3[j * 65 + lane],      fj, r0);
            r1 = fmaf(s_w3[j * 65 + lane + 32], fj, r1);
        }
        out[(size_t)(b * 64 + lane) * HW + q]      = fmaxf(r0, 0.f);
        out[(size_t)(b * 64 + lane + 32) * HW + q] = fmaxf(r1, 0.f);
        __syncwarp();
    }
}

// ---------------- launch ----------------
extern "C" void kernel_launch(void* const* d_in, const int* in_sizes, int n_in,
                              void* d_out, int out_size) {
    const float* uv  = (const float*)d_in[0];
    // d_in[1] = feat_2d : unused by the reference computation
    const float* f3d = (const float*)d_in[2];
    const float* w1  = (const float*)d_in[3];
    const float* b1  = (const float*)d_in[4];
    const float* w2  = (const float*)d_in[5];
    const float* b2  = (const float*)d_in[6];
    const float* w3  = (const float*)d_in[7];
    const float* b3  = (const float*)d_in[8];
    float* out = (float*)d_out;

    prep_kernel<<<512, 256>>>(uv, f3d);
    knn_kernel<<<dim3(HW / 64, BS), 256>>>();
    interp_kernel<<<(BS * HW) / 64, 256>>>(w1, b1, w2, b2, w3, b3, out);
}

// round 3
// speedup vs baseline: 3.4499x; 3.4499x over previous
#include <cuda_runtime.h>
#include <math.h>

#define BS 2
#define NPTS 8192
#define C3D 64
#define HH 64
#define WW 160
#define HW (HH*WW)
#define KNN 3

#define CW 80          // cells in x (2px each)
#define CHC 32         // cells in y
#define NCELL (CW*CHC)
#define CAP 48         // slots per cell

#define FLT_BIG 3.402823466e+38f

// ---------------- scratch ----------------
__device__ float4 g_pts[BS * NPTS];              // (x, y, s2_replica, 0)
__device__ int    g_cnt[BS * NCELL];
__device__ float4 g_cell[BS * NCELL * CAP];      // (x, y, s2_replica, idx_bits)
__device__ float  g_f3dT[BS * NPTS * C3D];       // point-major feat_3d
__device__ int4   g_knn[BS * HW];

// ---------------- zero counters ----------------
__global__ void zero_kernel() {
    int i = blockIdx.x * blockDim.x + threadIdx.x;
    if (i < BS * NCELL) g_cnt[i] = 0;
}

// ---------------- build: pack points + scatter into cells ----------------
__global__ void __launch_bounds__(256) build_kernel(const float* __restrict__ uv) {
    int i = blockIdx.x * blockDim.x + threadIdx.x;
    if (i >= BS * NPTS) return;
    int b = i >> 13;
    int n = i & (NPTS - 1);
    float ux = uv[(b * 2 + 0) * NPTS + n];
    float uy = uv[(b * 2 + 1) * NPTS + n];
    // replica of reference: s2 = RN(RN(ux*ux)+RN(uy*uy))
    float s2 = __fadd_rn(__fmul_rn(ux, ux), __fmul_rn(uy, uy));
    g_pts[i] = make_float4(ux, uy, s2, 0.0f);

    int cx = (int)(ux * 0.5f); cx = max(0, min(CW - 1, cx));
    int cy = (int)(uy * 0.5f); cy = max(0, min(CHC - 1, cy));
    int cell = (b * CHC + cy) * CW + cx;
    int slot = atomicAdd(&g_cnt[cell], 1);
    if (slot < CAP)
        g_cell[cell * CAP + slot] = make_float4(ux, uy, s2, __int_as_float(n));
}

// ---------------- coalesced transpose of feat_3d ----------------
__global__ void __launch_bounds__(256) transpose_kernel(const float* __restrict__ f3d) {
    __shared__ float tile[32][33];
    const int b  = blockIdx.z;
    const int c0 = blockIdx.y * 32;
    const int n0 = blockIdx.x * 32;
    const int tx = threadIdx.x, ty = threadIdx.y;   // (32, 8)
    #pragma unroll
    for (int k = 0; k < 4; ++k) {
        int c = c0 + ty + k * 8;
        tile[ty + k * 8][tx] = f3d[((size_t)(b * C3D + c)) * NPTS + n0 + tx];
    }
    __syncthreads();
    #pragma unroll
    for (int k = 0; k < 4; ++k) {
        int n = n0 + ty + k * 8;
        g_f3dT[((size_t)(b * NPTS + n)) * C3D + c0 + tx] = tile[tx][ty + k * 8];
    }
}

// ---------------- exact top-3 via expanding ring search ----------------
__device__ __forceinline__ bool lessMI(float ma, int ia, float mb, int ib) {
    return (ma < mb) || (ma == mb && ia < ib);
}

__device__ __forceinline__ void scan_cell(int b, int cx, int cy,
                                          float qxf, float qyf, float s1,
                                          float& d0, float& d1, float& d2v,
                                          int& j0, int& j1, int& j2) {
    if (cx < 0 || cx >= CW || cy < 0 || cy >= CHC) return;
    const int cell = (b * CHC + cy) * CW + cx;
    int cnt = g_cnt[cell]; if (cnt > CAP) cnt = CAP;
    const float4* __restrict__ base = &g_cell[cell * CAP];
    for (int s = 0; s < cnt; ++s) {
        const float4 p = __ldg(base + s);
        // replica of reference d2 rounding (validated bit-compatible)
        const float dot = __fmaf_rn(qyf, p.y, __fmul_rn(qxf, p.x));
        const float d2  = __fsub_rn(__fadd_rn(s1, p.z), __fmul_rn(2.0f, dot));
        const int   id  = __float_as_int(p.w);
        if (lessMI(d2, id, d2v, j2)) {
            if (lessMI(d2, id, d1, j1)) {
                d2v = d1; j2 = j1;
                if (lessMI(d2, id, d0, j0)) { d1 = d0; j1 = j0; d0 = d2; j0 = id; }
                else                        { d1 = d2; j1 = id; }
            } else { d2v = d2; j2 = id; }
        }
    }
}

__global__ void __launch_bounds__(256) knn_query_kernel() {
    const int tx = threadIdx.x & 31;
    const int ty = threadIdx.x >> 5;
    const int qx = blockIdx.x * 32 + tx;
    const int qy = blockIdx.y * 8 + ty;
    const int b  = blockIdx.z;

    const float qxf = (float)qx;
    const float qyf = (float)qy;
    const float s1  = __fadd_rn(__fmul_rn(qxf, qxf), __fmul_rn(qyf, qyf));
    const int cx = qx >> 1;
    const int cy = qy >> 1;

    float d0 = FLT_BIG, d1 = FLT_BIG, d2v = FLT_BIG;
    int   j0 = 0x7fffffff, j1 = 0x7fffffff, j2 = 0x7fffffff;

    scan_cell(b, cx, cy, qxf, qyf, s1, d0, d1, d2v, j0, j1, j2);

    for (int r = 1; r < 80; ++r) {
        // any point in a Chebyshev-r cell is >= 2*(r-1) px away (query on integer px)
        const float lb = 2.0f * (float)(r - 1);
        if (lb * lb > d2v + 0.5f) break;   // conservative: covers replica rounding error
        for (int dx = -r; dx <= r; ++dx) {
            scan_cell(b, cx + dx, cy - r, qxf, qyf, s1, d0, d1, d2v, j0, j1, j2);
            scan_cell(b, cx + dx, cy + r, qxf, qyf, s1, d0, d1, d2v, j0, j1, j2);
        }
        for (int dy = -r + 1; dy <= r - 1; ++dy) {
            scan_cell(b, cx - r, cy + dy, qxf, qyf, s1, d0, d1, d2v, j0, j1, j2);
            scan_cell(b, cx + r, cy + dy, qxf, qyf, s1, d0, d1, d2v, j0, j1, j2);
        }
    }

    g_knn[b * HW + qy * WW + qx] = make_int4(j0, j1, j2, 0);
}

// ---------------- phase 2: gather + MLP + score + w3 GEMM ----------------
__global__ void __launch_bounds__(256) interp_kernel(
    const float* __restrict__ w1, const float* __restrict__ b1,
    const float* __restrict__ w2, const float* __restrict__ b2,
    const float* __restrict__ w3, const float* __restrict__ b3,
    float* __restrict__ out) {

    __shared__ float s_w3[64 * 65];    // s_w3[j*65 + o] = w3[o][j]
    __shared__ float s_fin[8][64];

    const int lane = threadIdx.x & 31;
    const int wib  = threadIdx.x >> 5;
    const int gw   = (blockIdx.x * blockDim.x + threadIdx.x) >> 5;  // 0..2559

    for (int e = threadIdx.x; e < 64 * 64; e += 256) {
        int o = e >> 6, j = e & 63;
        s_w3[j * 65 + o] = w3[e];
    }

    float w1a = 0.f, w1b = 0.f, w1c = 0.f, b1v = 0.f;
    if (lane < 16) {
        w1a = w1[lane * 3 + 0];
        w1b = w1[lane * 3 + 1];
        w1c = w1[lane * 3 + 2];
        b1v = b1[lane];
    }
    float w2r0[16], w2r1[16];
    #pragma unroll
    for (int j = 0; j < 16; ++j) {
        w2r0[j] = w2[lane * 16 + j];
        w2r1[j] = w2[(lane + 32) * 16 + j];
    }
    const float b2a = b2[lane],  b2b = b2[lane + 32];
    const float b3a = b3[lane],  b3b = b3[lane + 32];
    __syncthreads();

    for (int qq = 0; qq < 8; ++qq) {
        const int gq = gw * 8 + qq;
        const int b  = gq / HW;
        const int q  = gq - b * HW;
        const float qx = (float)(q % WW);
        const float qy = (float)(q / WW);

        const int4 kn = g_knn[gq];

        float acc0 = 0.f, acc1 = 0.f;
        #pragma unroll
        for (int k = 0; k < KNN; ++k) {
            const int idx = (k == 0) ? kn.x : (k == 1) ? kn.y : kn.z;
            const float4 p = __ldg(&g_pts[b * NPTS + idx]);
            const float ox = p.x - qx;
            const float oy = p.y - qy;
            const float nr = sqrtf(ox * ox + oy * oy);
            float h = fmaf(w1a, ox, fmaf(w1b, oy, fmaf(w1c, nr, b1v)));
            h = fmaxf(h, 0.f);
            float e0 = b2a, e1 = b2b;
            #pragma unroll
            for (int j = 0; j < 16; ++j) {
                float hj = __shfl_sync(0xffffffffu, h, j);
                e0 = fmaf(w2r0[j], hj, e0);
                e1 = fmaf(w2r1[j], hj, e1);
            }
            const float s0 = 1.f / (1.f + __expf(-e0));
            const float s1v = 1.f / (1.f + __expf(-e1));
            const float* fp = g_f3dT + (size_t)(b * NPTS + idx) * C3D;
            acc0 = fmaf(s0,  __ldg(fp + lane),      acc0);
            acc1 = fmaf(s1v, __ldg(fp + lane + 32), acc1);
        }

        s_fin[wib][lane]      = acc0;
        s_fin[wib][lane + 32] = acc1;
        __syncwarp();

        float r0 = b3a, r1 = b3b;
        #pragma unroll 8
        for (int j = 0; j < 64; ++j) {
            float fj = s_fin[wib][j];
            r0 = fmaf(s_w3[j * 65 + lane],      fj, r0);
            r1 = fmaf(s_w3[j * 65 + lane + 32], fj, r1);
        }
        out[(size_t)(b * 64 + lane) * HW + q]      = fmaxf(r0, 0.f);
        out[(size_t)(b * 64 + lane + 32) * HW + q] = fmaxf(r1, 0.f);
        __syncwarp();
    }
}

// ---------------- launch ----------------
extern "C" void kernel_launch(void* const* d_in, const int* in_sizes, int n_in,
                              void* d_out, int out_size) {
    const float* uv  = (const float*)d_in[0];
    // d_in[1] = feat_2d : unused by the reference computation
    const float* f3d = (const float*)d_in[2];
    const float* w1  = (const float*)d_in[3];
    const float* b1  = (const float*)d_in[4];
    const float* w2  = (const float*)d_in[5];
    const float* b2  = (const float*)d_in[6];
    const float* w3  = (const float*)d_in[7];
    const float* b3  = (const float*)d_in[8];
    float* out = (float*)d_out;

    zero_kernel<<<(BS * NCELL + 255) / 256, 256>>>();
    build_kernel<<<(BS * NPTS + 255) / 256, 256>>>(uv);
    transpose_kernel<<<dim3(NPTS / 32, C3D / 32, BS), dim3(32, 8)>>>(f3d);
    knn_query_kernel<<<dim3(WW / 32, HH / 8, BS), 256>>>();
    interp_kernel<<<(BS * HW) / 64, 256>>>(w1, b1, w2, b2, w3, b3, out);
}

// round 4
// speedup vs baseline: 3.9679x; 1.1501x over previous
#include <cuda_runtime.h>
#include <math.h>

#define BS 2
#define NPTS 8192
#define C3D 64
#define HH 64
#define WW 160
#define HW (HH*WW)
#define KNN 3

#define CW 80          // cells in x (2px each)
#define CHC 32         // cells in y
#define NCELL (CW*CHC)
#define NTOT (BS*NCELL)

#define FLT_BIG 3.402823466e+38f

// ---------------- scratch ----------------
__device__ float4 g_pts[BS * NPTS];        // (x, y, s2_replica, 0) by original index
__device__ int    g_cnt[NTOT];             // zero-initialized; re-zeroed by interp each run
__device__ int    g_rowstart[NTOT + 1];
__device__ int    g_off[NTOT];
__device__ float4 g_cpts[BS * NPTS];       // CSR-compacted (x, y, s2, idx_bits)
__device__ float  g_f3dT[BS * NPTS * C3D]; // point-major feat_3d
__device__ int4   g_knn[BS * HW];

__device__ __forceinline__ int cell_of(float ux, float uy, int b) {
    int cx = (int)(ux * 0.5f); cx = max(0, min(CW - 1, cx));
    int cy = (int)(uy * 0.5f); cy = max(0, min(CHC - 1, cy));
    return (b * CHC + cy) * CW + cx;
}

// ---------------- K1: pack points + transpose feat_3d + count (fused) ----------
__global__ void __launch_bounds__(256) prep_kernel(const float* __restrict__ uv,
                                                   const float* __restrict__ f3d) {
    const int t = threadIdx.x;
    if (blockIdx.x < 1024) {
        // transpose: 32x32 tile, block acts as (32,8)
        __shared__ float tile[32][33];
        const int bid = blockIdx.x;
        const int b  = bid >> 9;
        const int c0 = ((bid >> 8) & 1) * 32;
        const int n0 = (bid & 255) * 32;
        const int tx = t & 31, ty = t >> 5;
        #pragma unroll
        for (int k = 0; k < 4; ++k)
            tile[ty + k * 8][tx] = f3d[((size_t)(b * C3D + c0 + ty + k * 8)) * NPTS + n0 + tx];
        __syncthreads();
        #pragma unroll
        for (int k = 0; k < 4; ++k)
            g_f3dT[((size_t)(b * NPTS + n0 + ty + k * 8)) * C3D + c0 + tx] = tile[tx][ty + k * 8];
    } else {
        // pack + count  (g_cnt zeroed by static init / previous interp)
        const int i = (blockIdx.x - 1024) * 256 + t;
        const int b = i >> 13;
        const int n = i & (NPTS - 1);
        const float ux = uv[(b * 2 + 0) * NPTS + n];
        const float uy = uv[(b * 2 + 1) * NPTS + n];
        const float s2 = __fadd_rn(__fmul_rn(ux, ux), __fmul_rn(uy, uy));
        g_pts[i] = make_float4(ux, uy, s2, 0.0f);
        atomicAdd(&g_cnt[cell_of(ux, uy, b)], 1);
    }
}

// ---------------- K2: exclusive scan over NTOT=5120 cells (one block) ----------
__global__ void __launch_bounds__(1024) scan_kernel() {
    const int t = threadIdx.x;
    int c[5], s = 0;
    #pragma unroll
    for (int k = 0; k < 5; ++k) { c[k] = g_cnt[t * 5 + k]; s += c[k]; }

    const int lane = t & 31, w = t >> 5;
    int v = s;
    #pragma unroll
    for (int o = 1; o < 32; o <<= 1) {
        int u = __shfl_up_sync(0xffffffffu, v, o);
        if (lane >= o) v += u;
    }
    __shared__ int ws[32];
    if (lane == 31) ws[w] = v;
    __syncthreads();
    if (w == 0) {
        int x = ws[lane];
        #pragma unroll
        for (int o = 1; o < 32; o <<= 1) {
            int u = __shfl_up_sync(0xffffffffu, x, o);
            if (lane >= o) x += u;
        }
        ws[lane] = x;
    }
    __syncthreads();
    int run = v - s + (w > 0 ? ws[w - 1] : 0);
    #pragma unroll
    for (int k = 0; k < 5; ++k) {
        g_rowstart[t * 5 + k] = run;
        g_off[t * 5 + k] = run;
        run += c[k];
    }
    if (t == 1023) g_rowstart[NTOT] = run;
}

// ---------------- K3: scatter into CSR ----------------
__global__ void __launch_bounds__(256) scatter_kernel() {
    const int i = blockIdx.x * 256 + threadIdx.x;
    const int b = i >> 13;
    const int n = i & (NPTS - 1);
    const float4 p = g_pts[i];
    const int slot = atomicAdd(&g_off[cell_of(p.x, p.y, b)], 1);
    g_cpts[slot] = make_float4(p.x, p.y, p.z, __int_as_float(n));
}

// ---------------- K4: exact top-3, 4 threads/query ----------------
__device__ __forceinline__ bool lessMI(float ma, int ia, float mb, int ib) {
    return (ma < mb) || (ma == mb && ia < ib);
}

__device__ __forceinline__ void ins(float d, int id,
                                    float& d0, float& d1, float& d2v,
                                    int& j0, int& j1, int& j2) {
    if (lessMI(d, id, d2v, j2)) {
        if (lessMI(d, id, d1, j1)) {
            d2v = d1; j2 = j1;
            if (lessMI(d, id, d0, j0)) { d1 = d0; j1 = j0; d0 = d; j0 = id; }
            else                       { d1 = d;  j1 = id; }
        } else { d2v = d; j2 = id; }
    }
}

__device__ __forceinline__ void scan_row(int b, int cy, int cxlo, int cxhi,
                                         float qxf, float qyf, float s1,
                                         float& d0, float& d1, float& d2v,
                                         int& j0, int& j1, int& j2) {
    if (cy < 0 || cy >= CHC) return;
    cxlo = max(cxlo, 0); cxhi = min(cxhi, CW - 1);
    if (cxlo > cxhi) return;
    const int rowbase = (b * CHC + cy) * CW;
    const int st = g_rowstart[rowbase + cxlo];
    const int en = g_rowstart[rowbase + cxhi + 1];
    for (int s = st; s < en; ++s) {
        const float4 p = __ldg(&g_cpts[s]);
        const float dot = __fmaf_rn(qyf, p.y, __fmul_rn(qxf, p.x));
        const float d2  = __fsub_rn(__fadd_rn(s1, p.z), __fmul_rn(2.0f, dot));
        ins(d2, __float_as_int(p.w), d0, d1, d2v, j0, j1, j2);
    }
}

__global__ void __launch_bounds__(256) knn_query_kernel() {
    const int t   = threadIdx.x;
    const int sub = t & 3;
    const int qb  = t >> 2;               // 0..63
    const int q   = blockIdx.x * 64 + qb; // 0..HW-1
    const int b   = blockIdx.y;

    const int qx = q % WW;
    const int qy = q / WW;
    const float qxf = (float)qx;
    const float qyf = (float)qy;
    const float s1 = __fadd_rn(__fmul_rn(qxf, qxf), __fmul_rn(qyf, qyf));
    const int cx = qx >> 1;
    const int cy = qy >> 1;

    float d0 = FLT_BIG, d1 = FLT_BIG, d2v = FLT_BIG;
    int   j0 = 0x7fffffff, j1 = 0x7fffffff, j2 = 0x7fffffff;

    // 5x5 neighborhood split across 4 sub-threads by row
    if (sub == 0) {
        scan_row(b, cy - 2, cx - 2, cx + 2, qxf, qyf, s1, d0, d1, d2v, j0, j1, j2);
        scan_row(b, cy + 2, cx - 2, cx + 2, qxf, qyf, s1, d0, d1, d2v, j0, j1, j2);
    } else {
        scan_row(b, cy - 2 + sub, cx - 2, cx + 2, qxf, qyf, s1, d0, d1, d2v, j0, j1, j2);
    }

    // merge top-3 across the 4-thread group (exact: total order on (d2, id))
    #pragma unroll
    for (int m = 1; m <= 2; m <<= 1) {
        float od0 = __shfl_xor_sync(0xffffffffu, d0,  m);
        float od1 = __shfl_xor_sync(0xffffffffu, d1,  m);
        float od2 = __shfl_xor_sync(0xffffffffu, d2v, m);
        int   oj0 = __shfl_xor_sync(0xffffffffu, j0,  m);
        int   oj1 = __shfl_xor_sync(0xffffffffu, j1,  m);
        int   oj2 = __shfl_xor_sync(0xffffffffu, j2,  m);
        ins(od0, oj0, d0, d1, d2v, j0, j1, j2);
        ins(od1, oj1, d0, d1, d2v, j0, j1, j2);
        ins(od2, oj2, d0, d1, d2v, j0, j1, j2);
    }

    if (sub == 0) {
        // rare exact fallback: ring-3 cells are >= 4px away
        for (int r = 3; r < 96; ++r) {
            const float lb = 2.0f * (float)(r - 1);
            if (lb * lb > d2v + 0.5f) break;
            scan_row(b, cy - r, cx - r, cx + r, qxf, qyf, s1, d0, d1, d2v, j0, j1, j2);
            scan_row(b, cy + r, cx - r, cx + r, qxf, qyf, s1, d0, d1, d2v, j0, j1, j2);
            for (int dy = -r + 1; dy <= r - 1; ++dy) {
                scan_row(b, cy + dy, cx - r, cx - r, qxf, qyf, s1, d0, d1, d2v, j0, j1, j2);
                scan_row(b, cy + dy, cx + r, cx + r, qxf, qyf, s1, d0, d1, d2v, j0, j1, j2);
            }
        }
        g_knn[b * HW + q] = make_int4(j0, j1, j2, 0);
    }
}

// ---------------- K5: gather + MLP + score + w3 GEMM (+ counter reset) --------
__global__ void __launch_bounds__(256) interp_kernel(
    const float* __restrict__ w1, const float* __restrict__ b1,
    const float* __restrict__ w2, const float* __restrict__ b2,
    const float* __restrict__ w3, const float* __restrict__ b3,
    float* __restrict__ out) {

    __shared__ float s_w3[64 * 65];      // s_w3[j*65 + o] = w3[o][j]
    __shared__ float s_fin[8][64];
    __shared__ float s_out[8][64][9];    // [warp][channel][query] (padded)

    const int lane = threadIdx.x & 31;
    const int wib  = threadIdx.x >> 5;
    const int gtid = blockIdx.x * blockDim.x + threadIdx.x;
    const int gw   = gtid >> 5;          // 0..2559

    // reset cell counters for the next pipeline invocation (deterministic:
    // static zero-init covers the first call, this covers every later call)
    if (gtid < NTOT) g_cnt[gtid] = 0;

    for (int e = threadIdx.x; e < 64 * 64; e += 256) {
        int o = e >> 6, j = e & 63;
        s_w3[j * 65 + o] = w3[e];
    }

    float w1a = 0.f, w1b = 0.f, w1c = 0.f, b1v = 0.f;
    if (lane < 16) {
        w1a = w1[lane * 3 + 0];
        w1b = w1[lane * 3 + 1];
        w1c = w1[lane * 3 + 2];
        b1v = b1[lane];
    }
    float w2r0[16], w2r1[16];
    #pragma unroll
    for (int j = 0; j < 16; ++j) {
        w2r0[j] = w2[lane * 16 + j];
        w2r1[j] = w2[(lane + 32) * 16 + j];
    }
    const float b2a = b2[lane],  b2b = b2[lane + 32];
    const float b3a = b3[lane],  b3b = b3[lane + 32];
    __syncthreads();

    const int gq0 = gw * 8;
    const int b   = gq0 / HW;
    const int q0  = gq0 - b * HW;

    for (int qq = 0; qq < 8; ++qq) {
        const int q  = q0 + qq;
        const float qx = (float)(q % WW);
        const float qy = (float)(q / WW);

        const int4 kn = g_knn[b * HW + q];

        float acc0 = 0.f, acc1 = 0.f;
        #pragma unroll
        for (int k = 0; k < KNN; ++k) {
            const int idx = (k == 0) ? kn.x : (k == 1) ? kn.y : kn.z;
            const float4 p = __ldg(&g_pts[b * NPTS + idx]);
            const float ox = p.x - qx;
            const float oy = p.y - qy;
            const float nr = sqrtf(ox * ox + oy * oy);
            float h = fmaf(w1a, ox, fmaf(w1b, oy, fmaf(w1c, nr, b1v)));
            h = fmaxf(h, 0.f);
            float e0 = b2a, e1 = b2b;
            #pragma unroll
            for (int j = 0; j < 16; ++j) {
                float hj = __shfl_sync(0xffffffffu, h, j);
                e0 = fmaf(w2r0[j], hj, e0);
                e1 = fmaf(w2r1[j], hj, e1);
            }
            const float s0  = 1.f / (1.f + __expf(-e0));
            const float s1v = 1.f / (1.f + __expf(-e1));
            const float* fp = g_f3dT + (size_t)(b * NPTS + idx) * C3D;
            acc0 = fmaf(s0,  __ldg(fp + lane),      acc0);
            acc1 = fmaf(s1v, __ldg(fp + lane + 32), acc1);
        }

        s_fin[wib][lane]      = acc0;
        s_fin[wib][lane + 32] = acc1;
        __syncwarp();

        float r0 = b3a, r1 = b3b;
        #pragma unroll 8
        for (int j = 0; j < 64; ++j) {
            float fj = s_fin[wib][j];
            r0 = fmaf(s_w3[j * 65 + lane],      fj, r0);
            r1 = fmaf(s_w3[j * 65 + lane + 32], fj, r1);
        }
        s_out[wib][lane][qq]      = fmaxf(r0, 0.f);
        s_out[wib][lane + 32][qq] = fmaxf(r1, 0.f);
        __syncwarp();
    }

    // coalesced flush: 64 channels x 8 queries as dense float4 pairs
    #pragma unroll
    for (int it = 0; it < 4; ++it) {
        const int item = it * 32 + lane;      // 0..127
        const int ch   = item >> 1;
        const int half = item & 1;
        float4 v;
        v.x = s_out[wib][ch][half * 4 + 0];
        v.y = s_out[wib][ch][half * 4 + 1];
        v.z = s_out[wib][ch][half * 4 + 2];
        v.w = s_out[wib][ch][half * 4 + 3];
        *reinterpret_cast<float4*>(out + (size_t)(b * 64 + ch) * HW + q0 + half * 4) = v;
    }
}

// ---------------- launch ----------------
extern "C" void kernel_launch(void* const* d_in, const int* in_sizes, int n_in,
                              void* d_out, int out_size) {
    const float* uv  = (const float*)d_in[0];
    // d_in[1] = feat_2d : unused by the reference computation
    const float* f3d = (const float*)d_in[2];
    const float* w1  = (const float*)d_in[3];
    const float* b1  = (const float*)d_in[4];
    const float* w2  = (const float*)d_in[5];
    const float* b2  = (const float*)d_in[6];
    const float* w3  = (const float*)d_in[7];
    const float* b3  = (const float*)d_in[8];
    float* out = (float*)d_out;

    prep_kernel<<<1024 + 64, 256>>>(uv, f3d);
    scan_kernel<<<1, 1024>>>();
    scatter_kernel<<<64, 256>>>();
    knn_query_kernel<<<dim3(HW / 64, BS), 256>>>();
    interp_kernel<<<(BS * HW) / 64, 256>>>(w1, b1, w2, b2, w3, b3, out);
}

// round 5
// speedup vs baseline: 5.1625x; 1.3011x over previous
#include <cuda_runtime.h>
#include <math.h>

#define BS 2
#define NPTS 8192
#define C3D 64
#define HH 64
#define WW 160
#define HW (HH*WW)
#define KNN 3

#define CW 80          // cells in x (2px each)
#define CHC 32         // cells in y
#define NCELL (CW*CHC)
#define NTOT (BS*NCELL)

#define FLT_BIG 3.402823466e+38f

// ---------------- scratch ----------------
__device__ float4 g_pts[BS * NPTS];        // (x, y, s2_replica, 0) by original index
__device__ int    g_cnt[NTOT];             // zero-init; re-zeroed by fused kernel each run
__device__ int    g_rowstart[NTOT + 1];
__device__ int    g_off[NTOT];
__device__ float4 g_cpts[BS * NPTS];       // CSR-compacted (x, y, s2, idx_bits)
__device__ float  g_f3dT[BS * NPTS * C3D]; // point-major feat_3d

__device__ __forceinline__ int cell_of(float ux, float uy, int b) {
    int cx = (int)(ux * 0.5f); cx = max(0, min(CW - 1, cx));
    int cy = (int)(uy * 0.5f); cy = max(0, min(CHC - 1, cy));
    return (b * CHC + cy) * CW + cx;
}

// ---------------- K1: transpose feat_3d (vectorized) + pack/count ----------
__global__ void __launch_bounds__(256) prep_kernel(const float* __restrict__ uv,
                                                   const float* __restrict__ f3d) {
    const int t = threadIdx.x;
    if (blockIdx.x < 1024) {
        __shared__ float tile[32][33];
        const int bid = blockIdx.x;
        const int b  = bid >> 9;
        const int c0 = ((bid >> 8) & 1) * 32;
        const int n0 = (bid & 255) * 32;
        const int tx2 = t & 7;         // float4 index
        const int row = t >> 3;        // 0..31
        // read: row = channel, float4 along n
        float4 v = *reinterpret_cast<const float4*>(
            f3d + ((size_t)(b * C3D + c0 + row)) * NPTS + n0 + tx2 * 4);
        tile[row][tx2 * 4 + 0] = v.x;  // stride-33: banks (row + 4*tx2 + i) -> conflict-free
        tile[row][tx2 * 4 + 1] = v.y;
        tile[row][tx2 * 4 + 2] = v.z;
        tile[row][tx2 * 4 + 3] = v.w;
        __syncthreads();
        // write: row = n, float4 along c
        const int n = t >> 3;
        float4 o;
        o.x = tile[tx2 * 4 + 0][n];
        o.y = tile[tx2 * 4 + 1][n];
        o.z = tile[tx2 * 4 + 2][n];
        o.w = tile[tx2 * 4 + 3][n];
        *reinterpret_cast<float4*>(
            g_f3dT + ((size_t)(b * NPTS + n0 + n)) * C3D + c0 + tx2 * 4) = o;
    } else {
        const int i = (blockIdx.x - 1024) * 256 + t;
        const int b = i >> 13;
        const int n = i & (NPTS - 1);
        const float ux = uv[(b * 2 + 0) * NPTS + n];
        const float uy = uv[(b * 2 + 1) * NPTS + n];
        const float s2 = __fadd_rn(__fmul_rn(ux, ux), __fmul_rn(uy, uy));
        g_pts[i] = make_float4(ux, uy, s2, 0.0f);
        atomicAdd(&g_cnt[cell_of(ux, uy, b)], 1);
    }
}

// ---------------- K2: exclusive scan over NTOT=5120 cells (one block) ----------
__global__ void __launch_bounds__(1024) scan_kernel() {
    const int t = threadIdx.x;
    int c[5], s = 0;
    #pragma unroll
    for (int k = 0; k < 5; ++k) { c[k] = g_cnt[t * 5 + k]; s += c[k]; }
    const int lane = t & 31, w = t >> 5;
    int v = s;
    #pragma unroll
    for (int o = 1; o < 32; o <<= 1) {
        int u = __shfl_up_sync(0xffffffffu, v, o);
        if (lane >= o) v += u;
    }
    __shared__ int ws[32];
    if (lane == 31) ws[w] = v;
    __syncthreads();
    if (w == 0) {
        int x = ws[lane];
        #pragma unroll
        for (int o = 1; o < 32; o <<= 1) {
            int u = __shfl_up_sync(0xffffffffu, x, o);
            if (lane >= o) x += u;
        }
        ws[lane] = x;
    }
    __syncthreads();
    int run = v - s + (w > 0 ? ws[w - 1] : 0);
    #pragma unroll
    for (int k = 0; k < 5; ++k) {
        g_rowstart[t * 5 + k] = run;
        g_off[t * 5 + k] = run;
        run += c[k];
    }
    if (t == 1023) g_rowstart[NTOT] = run;
}

// ---------------- K3: scatter into CSR ----------------
__global__ void __launch_bounds__(256) scatter_kernel() {
    const int i = blockIdx.x * 256 + threadIdx.x;
    const int b = i >> 13;
    const int n = i & (NPTS - 1);
    const float4 p = g_pts[i];
    const int slot = atomicAdd(&g_off[cell_of(p.x, p.y, b)], 1);
    g_cpts[slot] = make_float4(p.x, p.y, p.z, __int_as_float(n));
}

// ---------------- helpers ----------------
__device__ __forceinline__ bool lessMI(float ma, int ia, float mb, int ib) {
    return (ma < mb) || (ma == mb && ia < ib);
}
__device__ __forceinline__ void ins(float d, int id,
                                    float& d0, float& d1, float& d2v,
                                    int& j0, int& j1, int& j2) {
    if (lessMI(d, id, d2v, j2)) {
        if (lessMI(d, id, d1, j1)) {
            d2v = d1; j2 = j1;
            if (lessMI(d, id, d0, j0)) { d1 = d0; j1 = j0; d0 = d; j0 = id; }
            else                       { d1 = d;  j1 = id; }
        } else { d2v = d; j2 = id; }
    }
}
__device__ __forceinline__ void scan_span(int st, int en, int stride,
                                          float qxf, float qyf, float s1,
                                          float& d0, float& d1, float& d2v,
                                          int& j0, int& j1, int& j2) {
    for (int s = st; s < en; s += stride) {
        const float4 p = __ldg(&g_cpts[s]);
        const float dot = __fmaf_rn(qyf, p.y, __fmul_rn(qxf, p.x));
        const float d2  = __fsub_rn(__fadd_rn(s1, p.z), __fmul_rn(2.0f, dot));
        ins(d2, __float_as_int(p.w), d0, d1, d2v, j0, j1, j2);
    }
}
__device__ __forceinline__ void row_bounds(int b, int cy, int cxlo, int cxhi,
                                           int& st, int& en) {
    st = 0; en = 0;
    if (cy < 0 || cy >= CHC) return;
    cxlo = max(cxlo, 0); cxhi = min(cxhi, CW - 1);
    if (cxlo > cxhi) return;
    const int rowbase = (b * CHC + cy) * CW;
    st = g_rowstart[rowbase + cxlo];
    en = g_rowstart[rowbase + cxhi + 1];
}

// ---------------- K4: fused knn + gather/MLP + w3 block-GEMM ----------------
__global__ void __launch_bounds__(256) fused_kernel(
    const float* __restrict__ w1, const float* __restrict__ b1,
    const float* __restrict__ w2, const float* __restrict__ b2,
    const float* __restrict__ w3, const float* __restrict__ b3,
    float* __restrict__ out) {

    __shared__ float s_w3[64 * 68];    // [j*68 + o] = w3[o][j]
    __shared__ float s_fin[64 * 68];   // [j*68 + q_local]

    const int t    = threadIdx.x;
    const int lane = t & 31;
    const int wib  = t >> 5;
    const int b    = blockIdx.y;
    const int q0   = blockIdx.x * 64;

    // reset cell counters for next invocation (consumed earlier this run by scan)
    const int gtid = (blockIdx.y * gridDim.x + blockIdx.x) * 256 + t;
    if (gtid < NTOT) g_cnt[gtid] = 0;

    // stage w3 transposed (coalesced gmem reads)
    for (int e = t; e < 64 * 64; e += 256) {
        int o = e >> 6, j = e & 63;
        s_w3[j * 68 + o] = w3[e];
    }

    // ---- phase A: knn, 4 lanes per query, column-strided 3x3 scan ----
    const int sub = lane & 3;
    const int qq0 = lane >> 2;               // 0..7
    const int q   = q0 + wib * 8 + qq0;
    const int qx  = q % WW;
    const int qy  = q / WW;
    const float qxf = (float)qx;
    const float qyf = (float)qy;
    const float s1  = __fadd_rn(__fmul_rn(qxf, qxf), __fmul_rn(qyf, qyf));
    const int cx = qx >> 1;
    const int cy = qy >> 1;

    float d0 = FLT_BIG, d1 = FLT_BIG, d2v = FLT_BIG;
    int   j0 = 0x7fffffff, j1 = 0x7fffffff, j2 = 0x7fffffff;

    #pragma unroll
    for (int dy = -1; dy <= 1; ++dy) {
        int st, en;
        row_bounds(b, cy + dy, cx - 1, cx + 1, st, en);
        scan_span(st + sub, en, 4, qxf, qyf, s1, d0, d1, d2v, j0, j1, j2);
    }

    // merge across the 4-lane group
    #pragma unroll
    for (int m = 1; m <= 2; m <<= 1) {
        float od0 = __shfl_xor_sync(0xffffffffu, d0,  m);
        float od1 = __shfl_xor_sync(0xffffffffu, d1,  m);
        float od2 = __shfl_xor_sync(0xffffffffu, d2v, m);
        int   oj0 = __shfl_xor_sync(0xffffffffu, j0,  m);
        int   oj1 = __shfl_xor_sync(0xffffffffu, j1,  m);
        int   oj2 = __shfl_xor_sync(0xffffffffu, j2,  m);
        ins(od0, oj0, d0, d1, d2v, j0, j1, j2);
        ins(od1, oj1, d0, d1, d2v, j0, j1, j2);
        ins(od2, oj2, d0, d1, d2v, j0, j1, j2);
    }

    // rare exact fallback: 3x3 guarantees >=2px coverage; trust iff d2v+0.5 < 4
    if (sub == 0 && d2v + 0.5f >= 4.0f) {
        for (int r = 2; r < 96; ++r) {
            const float lb = 2.0f * (float)(r - 1);
            if (lb * lb > d2v + 0.5f) break;
            int st, en;
            row_bounds(b, cy - r, cx - r, cx + r, st, en);
            scan_span(st, en, 1, qxf, qyf, s1, d0, d1, d2v, j0, j1, j2);
            row_bounds(b, cy + r, cx - r, cx + r, st, en);
            scan_span(st, en, 1, qxf, qyf, s1, d0, d1, d2v, j0, j1, j2);
            for (int dy = -r + 1; dy <= r - 1; ++dy) {
                row_bounds(b, cy + dy, cx - r, cx - r, st, en);
                scan_span(st, en, 1, qxf, qyf, s1, d0, d1, d2v, j0, j1, j2);
                row_bounds(b, cy + dy, cx + r, cx + r, st, en);
                scan_span(st, en, 1, qxf, qyf, s1, d0, d1, d2v, j0, j1, j2);
            }
        }
    }

    // ---- phase B: gather + MLP (warp = 8 queries jointly) ----
    float w1a = 0.f, w1b = 0.f, w1c = 0.f, b1v = 0.f;
    if (lane < 16) {
        w1a = w1[lane * 3 + 0];
        w1b = w1[lane * 3 + 1];
        w1c = w1[lane * 3 + 2];
        b1v = b1[lane];
    }
    float w2r0[16], w2r1[16];
    #pragma unroll
    for (int j = 0; j < 16; ++j) {
        w2r0[j] = w2[lane * 16 + j];
        w2r1[j] = w2[(lane + 32) * 16 + j];
    }
    const float b2a = b2[lane], b2b = b2[lane + 32];

    float acc0q[8], acc1q[8];
    #pragma unroll
    for (int qq = 0; qq < 8; ++qq) {
        const int src = qq << 2;
        const int k0 = __shfl_sync(0xffffffffu, j0, src);
        const int k1 = __shfl_sync(0xffffffffu, j1, src);
        const int k2 = __shfl_sync(0xffffffffu, j2, src);
        const int mq = q0 + wib * 8 + qq;
        const float mqx = (float)(mq % WW);
        const float mqy = (float)(mq / WW);

        float a0 = 0.f, a1 = 0.f;
        #pragma unroll
        for (int k = 0; k < KNN; ++k) {
            const int idx = (k == 0) ? k0 : (k == 1) ? k1 : k2;
            const float4 p = __ldg(&g_pts[b * NPTS + idx]);
            const float ox = p.x - mqx;
            const float oy = p.y - mqy;
            const float nr = sqrtf(ox * ox + oy * oy);
            float h = fmaf(w1a, ox, fmaf(w1b, oy, fmaf(w1c, nr, b1v)));
            h = fmaxf(h, 0.f);
            float e0 = b2a, e1 = b2b;
            #pragma unroll
            for (int j = 0; j < 16; ++j) {
                float hj = __shfl_sync(0xffffffffu, h, j);
                e0 = fmaf(w2r0[j], hj, e0);
                e1 = fmaf(w2r1[j], hj, e1);
            }
            const float s0  = 1.f / (1.f + __expf(-e0));
            const float s1v = 1.f / (1.f + __expf(-e1));
            const float* fp = g_f3dT + (size_t)(b * NPTS + idx) * C3D;
            a0 = fmaf(s0,  __ldg(fp + lane),      a0);
            a1 = fmaf(s1v, __ldg(fp + lane + 32), a1);
        }
        acc0q[qq] = a0;
        acc1q[qq] = a1;
    }

    // lane owns rows j=lane and j=lane+32: write 8 queries as float4 pairs
    {
        float* r0 = &s_fin[lane * 68 + wib * 8];
        float* r1 = &s_fin[(lane + 32) * 68 + wib * 8];
        *reinterpret_cast<float4*>(r0)     = make_float4(acc0q[0], acc0q[1], acc0q[2], acc0q[3]);
        *reinterpret_cast<float4*>(r0 + 4) = make_float4(acc0q[4], acc0q[5], acc0q[6], acc0q[7]);
        *reinterpret_cast<float4*>(r1)     = make_float4(acc1q[0], acc1q[1], acc1q[2], acc1q[3]);
        *reinterpret_cast<float4*>(r1 + 4) = make_float4(acc1q[4], acc1q[5], acc1q[6], acc1q[7]);
    }
    __syncthreads();

    // ---- phase C: w3 block GEMM, 4x4 register tile per thread ----
    {
        const int tx = t & 15;          // q4 = tx*4
        const int ty = t >> 4;          // o0 = ty*4
        const int o0 = ty * 4;
        const int q4 = tx * 4;
        float r00[4], r01[4], r02[4], r03[4];
        const float bz0 = __ldg(b3 + o0 + 0);
        const float bz1 = __ldg(b3 + o0 + 1);
        const float bz2 = __ldg(b3 + o0 + 2);
        const float bz3 = __ldg(b3 + o0 + 3);
        #pragma unroll
        for (int k = 0; k < 4; ++k) { r00[k] = bz0; r01[k] = bz1; r02[k] = bz2; r03[k] = bz3; }

        #pragma unroll 4
        for (int j = 0; j < 64; ++j) {
            const float4 wv = *reinterpret_cast<const float4*>(&s_w3[j * 68 + o0]);
            const float4 fv = *reinterpret_cast<const float4*>(&s_fin[j * 68 + q4]);
            r00[0] = fmaf(wv.x, fv.x, r00[0]); r00[1] = fmaf(wv.x, fv.y, r00[1]);
            r00[2] = fmaf(wv.x, fv.z, r00[2]); r00[3] = fmaf(wv.x, fv.w, r00[3]);
            r01[0] = fmaf(wv.y, fv.x, r01[0]); r01[1] = fmaf(wv.y, fv.y, r01[1]);
            r01[2] = fmaf(wv.y, fv.z, r01[2]); r01[3] = fmaf(wv.y, fv.w, r01[3]);
            r02[0] = fmaf(wv.z, fv.x, r02[0]); r02[1] = fmaf(wv.z, fv.y, r02[1]);
            r02[2] = fmaf(wv.z, fv.z, r02[2]); r02[3] = fmaf(wv.z, fv.w, r02[3]);
            r03[0] = fmaf(wv.w, fv.x, r03[0]); r03[1] = fmaf(wv.w, fv.y, r03[1]);
            r03[2] = fmaf(wv.w, fv.z, r03[2]); r03[3] = fmaf(wv.w, fv.w, r03[3]);
        }
        float* op = out + (size_t)(b * 64 + o0) * HW + q0 + q4;
        *reinterpret_cast<float4*>(op) =
            make_float4(fmaxf(r00[0],0.f), fmaxf(r00[1],0.f), fmaxf(r00[2],0.f), fmaxf(r00[3],0.f));
        *reinterpret_cast<float4*>(op + HW) =
            make_float4(fmaxf(r01[0],0.f), fmaxf(r01[1],0.f), fmaxf(r01[2],0.f), fmaxf(r01[3],0.f));
        *reinterpret_cast<float4*>(op + 2 * HW) =
            make_float4(fmaxf(r02[0],0.f), fmaxf(r02[1],0.f), fmaxf(r02[2],0.f), fmaxf(r02[3],0.f));
        *reinterpret_cast<float4*>(op + 3 * HW) =
            make_float4(fmaxf(r03[0],0.f), fmaxf(r03[1],0.f), fmaxf(r03[2],0.f), fmaxf(r03[3],0.f));
    }
}

// ---------------- launch ----------------
extern "C" void kernel_launch(void* const* d_in, const int* in_sizes, int n_in,
                              void* d_out, int out_size) {
    const float* uv  = (const float*)d_in[0];
    // d_in[1] = feat_2d : unused by the reference computation
    const float* f3d = (const float*)d_in[2];
    const float* w1  = (const float*)d_in[3];
    const float* b1  = (const float*)d_in[4];
    const float* w2  = (const float*)d_in[5];
    const float* b2  = (const float*)d_in[6];
    const float* w3  = (const float*)d_in[7];
    const float* b3  = (const float*)d_in[8];
    float* out = (float*)d_out;

    prep_kernel<<<1024 + 64, 256>>>(uv, f3d);
    scan_kernel<<<1, 1024>>>();
    scatter_kernel<<<64, 256>>>();
    fused_kernel<<<dim3(HW / 64, BS), 256>>>(w1, b1, w2, b2, w3, b3, out);
}

// round 7
// speedup vs baseline: 5.3379x; 1.0340x over previous
#include <cuda_runtime.h>
#include <math.h>

#define BS 2
#define NPTS 8192
#define C3D 64
#define HH 64
#define WW 160
#define HW (HH*WW)
#define KNN 3

#define CW 80          // cells in x (2px each)
#define CHC 32         // cells in y
#define NCELL (CW*CHC)
#define NTOT (BS*NCELL)

#define FLT_BIG 3.402823466e+38f

// ---------------- scratch ----------------
__device__ float4 g_pts[BS * NPTS];        // (x, y, s2_replica, 0) by original index
__device__ int    g_cnt[NTOT];             // zero-init; re-zeroed by fused kernel each run
__device__ int    g_rowstart[NTOT + 1];
__device__ int    g_off[NTOT];
__device__ float4 g_cpts[BS * NPTS];       // CSR-compacted (x, y, s2, idx_bits)
__device__ float  g_f3dT[BS * NPTS * C3D]; // point-major feat_3d

__device__ __forceinline__ int cell_of(float ux, float uy, int b) {
    int cx = (int)(ux * 0.5f); cx = max(0, min(CW - 1, cx));
    int cy = (int)(uy * 0.5f); cy = max(0, min(CHC - 1, cy));
    return (b * CHC + cy) * CW + cx;
}

// ---------------- K1: transpose feat_3d (vectorized) + pack/count ----------
__global__ void __launch_bounds__(256) prep_kernel(const float* __restrict__ uv,
                                                   const float* __restrict__ f3d) {
    const int t = threadIdx.x;
    if (blockIdx.x < 1024) {
        __shared__ float tile[32][33];
        const int bid = blockIdx.x;
        const int b  = bid >> 9;
        const int c0 = ((bid >> 8) & 1) * 32;
        const int n0 = (bid & 255) * 32;
        const int tx2 = t & 7;
        const int row = t >> 3;
        float4 v = *reinterpret_cast<const float4*>(
            f3d + ((size_t)(b * C3D + c0 + row)) * NPTS + n0 + tx2 * 4);
        tile[row][tx2 * 4 + 0] = v.x;
        tile[row][tx2 * 4 + 1] = v.y;
        tile[row][tx2 * 4 + 2] = v.z;
        tile[row][tx2 * 4 + 3] = v.w;
        __syncthreads();
        const int n = t >> 3;
        float4 o;
        o.x = tile[tx2 * 4 + 0][n];
        o.y = tile[tx2 * 4 + 1][n];
        o.z = tile[tx2 * 4 + 2][n];
        o.w = tile[tx2 * 4 + 3][n];
        *reinterpret_cast<float4*>(
            g_f3dT + ((size_t)(b * NPTS + n0 + n)) * C3D + c0 + tx2 * 4) = o;
    } else {
        const int i = (blockIdx.x - 1024) * 256 + t;
        const int b = i >> 13;
        const int n = i & (NPTS - 1);
        const float ux = uv[(b * 2 + 0) * NPTS + n];
        const float uy = uv[(b * 2 + 1) * NPTS + n];
        const float s2 = __fadd_rn(__fmul_rn(ux, ux), __fmul_rn(uy, uy));
        g_pts[i] = make_float4(ux, uy, s2, 0.0f);
        atomicAdd(&g_cnt[cell_of(ux, uy, b)], 1);
    }
}

// ---------------- K2: exclusive scan over NTOT=5120 cells (one block) ----------
__global__ void __launch_bounds__(1024) scan_kernel() {
    const int t = threadIdx.x;
    int c[5], s = 0;
    #pragma unroll
    for (int k = 0; k < 5; ++k) { c[k] = g_cnt[t * 5 + k]; s += c[k]; }
    const int lane = t & 31, w = t >> 5;
    int v = s;
    #pragma unroll
    for (int o = 1; o < 32; o <<= 1) {
        int u = __shfl_up_sync(0xffffffffu, v, o);
        if (lane >= o) v += u;
    }
    __shared__ int ws[32];
    if (lane == 31) ws[w] = v;
    __syncthreads();
    if (w == 0) {
        int x = ws[lane];
        #pragma unroll
        for (int o = 1; o < 32; o <<= 1) {
            int u = __shfl_up_sync(0xffffffffu, x, o);
            if (lane >= o) x += u;
        }
        ws[lane] = x;
    }
    __syncthreads();
    int run = v - s + (w > 0 ? ws[w - 1] : 0);
    #pragma unroll
    for (int k = 0; k < 5; ++k) {
        g_rowstart[t * 5 + k] = run;
        g_off[t * 5 + k] = run;
        run += c[k];
    }
    if (t == 1023) g_rowstart[NTOT] = run;
}

// ---------------- K3: scatter into CSR ----------------
__global__ void __launch_bounds__(256) scatter_kernel() {
    const int i = blockIdx.x * 256 + threadIdx.x;
    const int b = i >> 13;
    const int n = i & (NPTS - 1);
    const float4 p = g_pts[i];
    const int slot = atomicAdd(&g_off[cell_of(p.x, p.y, b)], 1);
    g_cpts[slot] = make_float4(p.x, p.y, p.z, __int_as_float(n));
}

// ---------------- helpers ----------------
__device__ __forceinline__ bool lessMI(float ma, int ia, float mb, int ib) {
    return (ma < mb) || (ma == mb && ia < ib);
}
__device__ __forceinline__ void ins(float d, int id,
                                    float& d0, float& d1, float& d2v,
                                    int& j0, int& j1, int& j2) {
    if (lessMI(d, id, d2v, j2)) {
        if (lessMI(d, id, d1, j1)) {
            d2v = d1; j2 = j1;
            if (lessMI(d, id, d0, j0)) { d1 = d0; j1 = j0; d0 = d; j0 = id; }
            else                       { d1 = d;  j1 = id; }
        } else { d2v = d; j2 = id; }
    }
}
__device__ __forceinline__ void scan_span(int st, int en, int stride,
                                          float qxf, float qyf, float s1,
                                          float& d0, float& d1, float& d2v,
                                          int& j0, int& j1, int& j2) {
    for (int s = st; s < en; s += stride) {
        const float4 p = __ldg(&g_cpts[s]);
        const float dot = __fmaf_rn(qyf, p.y, __fmul_rn(qxf, p.x));
        const float d2  = __fsub_rn(__fadd_rn(s1, p.z), __fmul_rn(2.0f, dot));
        ins(d2, __float_as_int(p.w), d0, d1, d2v, j0, j1, j2);
    }
}
__device__ __forceinline__ void row_bounds(int b, int cy, int cxlo, int cxhi,
                                           int& st, int& en) {
    st = 0; en = 0;
    if (cy < 0 || cy >= CHC) return;
    cxlo = max(cxlo, 0); cxhi = min(cxhi, CW - 1);
    if (cxlo > cxhi) return;
    const int rowbase = (b * CHC + cy) * CW;
    st = g_rowstart[rowbase + cxlo];
    en = g_rowstart[rowbase + cxhi + 1];
}

// ---------------- K4: fused knn + block-parallel MLP + w3 block-GEMM ----------
// smem: s_w3 17408B + union(s_H 15360B / s_fin 17408B) 17408B + knn/w1/b1 ~1.3KB = ~36.1KB
__global__ void __launch_bounds__(256) fused_kernel(
    const float* __restrict__ w1, const float* __restrict__ b1,
    const float* __restrict__ w2, const float* __restrict__ b2,
    const float* __restrict__ w3, const float* __restrict__ b3,
    float* __restrict__ out) {

    __shared__ float s_w3[64 * 68];    // [j*68 + o] = w3[o][j]
    __shared__ float s_buf[64 * 68];   // union: s_H [qk*20+j] then s_fin [j*68+q]
    __shared__ int4  s_knn[64];
    __shared__ float s_w1[48];
    __shared__ float s_b1[16];

    float* const s_H   = s_buf;        // 192*20 = 3840 floats (fits in 4352)
    float* const s_fin = s_buf;        // 64*68 floats, live after s_H retires

    const int t    = threadIdx.x;
    const int lane = t & 31;
    const int wib  = t >> 5;
    const int b    = blockIdx.y;
    const int q0   = blockIdx.x * 64;

    // reset cell counters for next invocation (consumed earlier this run by scan)
    const int gtid = (blockIdx.y * gridDim.x + blockIdx.x) * 256 + t;
    if (gtid < NTOT) g_cnt[gtid] = 0;

    if (t < 48) s_w1[t] = w1[t];
    if (t < 16) s_b1[t] = b1[t];

    // stage w3 transposed (coalesced gmem reads)
    for (int e = t; e < 64 * 64; e += 256) {
        int o = e >> 6, j = e & 63;
        s_w3[j * 68 + o] = w3[e];
    }

    // ---- phase A: knn, 4 lanes per query, column-strided 3x3 scan ----
    const int sub = lane & 3;
    const int qq0 = lane >> 2;               // 0..7
    const int q   = q0 + wib * 8 + qq0;
    const int qx  = q % WW;
    const int qy  = q / WW;
    const float qxf = (float)qx;
    const float qyf = (float)qy;
    const float s1  = __fadd_rn(__fmul_rn(qxf, qxf), __fmul_rn(qyf, qyf));
    const int cx = qx >> 1;
    const int cy = qy >> 1;

    float d0 = FLT_BIG, d1 = FLT_BIG, d2v = FLT_BIG;
    int   j0 = 0x7fffffff, j1 = 0x7fffffff, j2 = 0x7fffffff;

    #pragma unroll
    for (int dy = -1; dy <= 1; ++dy) {
        int st, en;
        row_bounds(b, cy + dy, cx - 1, cx + 1, st, en);
        scan_span(st + sub, en, 4, qxf, qyf, s1, d0, d1, d2v, j0, j1, j2);
    }

    #pragma unroll
    for (int m = 1; m <= 2; m <<= 1) {
        float od0 = __shfl_xor_sync(0xffffffffu, d0,  m);
        float od1 = __shfl_xor_sync(0xffffffffu, d1,  m);
        float od2 = __shfl_xor_sync(0xffffffffu, d2v, m);
        int   oj0 = __shfl_xor_sync(0xffffffffu, j0,  m);
        int   oj1 = __shfl_xor_sync(0xffffffffu, j1,  m);
        int   oj2 = __shfl_xor_sync(0xffffffffu, j2,  m);
        ins(od0, oj0, d0, d1, d2v, j0, j1, j2);
        ins(od1, oj1, d0, d1, d2v, j0, j1, j2);
        ins(od2, oj2, d0, d1, d2v, j0, j1, j2);
    }

    if (sub == 0) {
        // rare exact fallback: 3x3 guarantees >=2px coverage; trust iff d2v+0.5 < 4
        if (d2v + 0.5f >= 4.0f) {
            for (int r = 2; r < 96; ++r) {
                const float lb = 2.0f * (float)(r - 1);
                if (lb * lb > d2v + 0.5f) break;
                int st, en;
                row_bounds(b, cy - r, cx - r, cx + r, st, en);
                scan_span(st, en, 1, qxf, qyf, s1, d0, d1, d2v, j0, j1, j2);
                row_bounds(b, cy + r, cx - r, cx + r, st, en);
                scan_span(st, en, 1, qxf, qyf, s1, d0, d1, d2v, j0, j1, j2);
                for (int dy = -r + 1; dy <= r - 1; ++dy) {
                    row_bounds(b, cy + dy, cx - r, cx - r, st, en);
                    scan_span(st, en, 1, qxf, qyf, s1, d0, d1, d2v, j0, j1, j2);
                    row_bounds(b, cy + dy, cx + r, cx + r, st, en);
                    scan_span(st, en, 1, qxf, qyf, s1, d0, d1, d2v, j0, j1, j2);
                }
            }
        }
        s_knn[wib * 8 + qq0] = make_int4(j0, j1, j2, 0);
    }
    __syncthreads();

    // ---- phase B1: hidden layer, one thread per (query,k) pair ----
    if (t < 192) {
        const int lq = t / 3;
        const int k  = t - lq * 3;
        const int4 kn = s_knn[lq];
        const int idx = (k == 0) ? kn.x : (k == 1) ? kn.y : kn.z;
        const float4 p = __ldg(&g_pts[b * NPTS + idx]);
        const int mq = q0 + lq;
        const float mqx = (float)(mq % WW);
        const float mqy = (float)(mq / WW);
        const float ox = p.x - mqx;
        const float oy = p.y - mqy;
        const float nr = sqrtf(ox * ox + oy * oy);
        #pragma unroll
        for (int j = 0; j < 16; j += 4) {
            float4 hv;
            hv.x = fmaxf(fmaf(s_w1[(j+0)*3], ox, fmaf(s_w1[(j+0)*3+1], oy, fmaf(s_w1[(j+0)*3+2], nr, s_b1[j+0]))), 0.f);
            hv.y = fmaxf(fmaf(s_w1[(j+1)*3], ox, fmaf(s_w1[(j+1)*3+1], oy, fmaf(s_w1[(j+1)*3+2], nr, s_b1[j+1]))), 0.f);
            hv.z = fmaxf(fmaf(s_w1[(j+2)*3], ox, fmaf(s_w1[(j+2)*3+1], oy, fmaf(s_w1[(j+2)*3+2], nr, s_b1[j+2]))), 0.f);
            hv.w = fmaxf(fmaf(s_w1[(j+3)*3], ox, fmaf(s_w1[(j+3)*3+1], oy, fmaf(s_w1[(j+3)*3+2], nr, s_b1[j+3]))), 0.f);
            *reinterpret_cast<float4*>(&s_H[t * 20 + j]) = hv;
        }
    }

    // per-lane w2 rows (overlaps with B1 compute)
    float w2r0[16], w2r1[16];
    #pragma unroll
    for (int j = 0; j < 16; ++j) {
        w2r0[j] = w2[lane * 16 + j];
        w2r1[j] = w2[(lane + 32) * 16 + j];
    }
    const float b2a = b2[lane], b2b = b2[lane + 32];
    __syncthreads();

    // ---- phase B2: score + gather (warp = 8 queries, lane = 2 channels) ----
    float acc0q[8], acc1q[8];
    #pragma unroll
    for (int qq = 0; qq < 8; ++qq) {
        const int lq = wib * 8 + qq;
        const int4 kn = s_knn[lq];
        float a0 = 0.f, a1 = 0.f;
        #pragma unroll
        for (int k = 0; k < KNN; ++k) {
            const int idx = (k == 0) ? kn.x : (k == 1) ? kn.y : kn.z;
            const float* hp = &s_H[(lq * 3 + k) * 20];
            const float4 h0 = *reinterpret_cast<const float4*>(hp);
            const float4 h1 = *reinterpret_cast<const float4*>(hp + 4);
            const float4 h2 = *reinterpret_cast<const float4*>(hp + 8);
            const float4 h3 = *reinterpret_cast<const float4*>(hp + 12);
            float e0 = b2a, e1 = b2b;
            e0 = fmaf(w2r0[0],  h0.x, e0); e1 = fmaf(w2r1[0],  h0.x, e1);
            e0 = fmaf(w2r0[1],  h0.y, e0); e1 = fmaf(w2r1[1],  h0.y, e1);
            e0 = fmaf(w2r0[2],  h0.z, e0); e1 = fmaf(w2r1[2],  h0.z, e1);
            e0 = fmaf(w2r0[3],  h0.w, e0); e1 = fmaf(w2r1[3],  h0.w, e1);
            e0 = fmaf(w2r0[4],  h1.x, e0); e1 = fmaf(w2r1[4],  h1.x, e1);
            e0 = fmaf(w2r0[5],  h1.y, e0); e1 = fmaf(w2r1[5],  h1.y, e1);
            e0 = fmaf(w2r0[6],  h1.z, e0); e1 = fmaf(w2r1[6],  h1.z, e1);
            e0 = fmaf(w2r0[7],  h1.w, e0); e1 = fmaf(w2r1[7],  h1.w, e1);
            e0 = fmaf(w2r0[8],  h2.x, e0); e1 = fmaf(w2r1[8],  h2.x, e1);
            e0 = fmaf(w2r0[9],  h2.y, e0); e1 = fmaf(w2r1[9],  h2.y, e1);
            e0 = fmaf(w2r0[10], h2.z, e0); e1 = fmaf(w2r1[10], h2.z, e1);
            e0 = fmaf(w2r0[11], h2.w, e0); e1 = fmaf(w2r1[11], h2.w, e1);
            e0 = fmaf(w2r0[12], h3.x, e0); e1 = fmaf(w2r1[12], h3.x, e1);
            e0 = fmaf(w2r0[13], h3.y, e0); e1 = fmaf(w2r1[13], h3.y, e1);
            e0 = fmaf(w2r0[14], h3.z, e0); e1 = fmaf(w2r1[14], h3.z, e1);
            e0 = fmaf(w2r0[15], h3.w, e0); e1 = fmaf(w2r1[15], h3.w, e1);
            const float s0  = 1.f / (1.f + __expf(-e0));
            const float s1v = 1.f / (1.f + __expf(-e1));
            const float* fp = g_f3dT + (size_t)(b * NPTS + idx) * C3D;
            a0 = fmaf(s0,  __ldg(fp + lane),      a0);
            a1 = fmaf(s1v, __ldg(fp + lane + 32), a1);
        }
        acc0q[qq] = a0;
        acc1q[qq] = a1;
    }
    __syncthreads();   // all reads of s_H complete before aliased s_fin writes

    {
        float* r0 = &s_fin[lane * 68 + wib * 8];
        float* r1 = &s_fin[(lane + 32) * 68 + wib * 8];
        *reinterpret_cast<float4*>(r0)     = make_float4(acc0q[0], acc0q[1], acc0q[2], acc0q[3]);
        *reinterpret_cast<float4*>(r0 + 4) = make_float4(acc0q[4], acc0q[5], acc0q[6], acc0q[7]);
        *reinterpret_cast<float4*>(r1)     = make_float4(acc1q[0], acc1q[1], acc1q[2], acc1q[3]);
        *reinterpret_cast<float4*>(r1 + 4) = make_float4(acc1q[4], acc1q[5], acc1q[6], acc1q[7]);
    }
    __syncthreads();

    // ---- phase C: w3 block GEMM, 4x4 register tile per thread ----
    {
        const int tx = t & 15;
        const int ty = t >> 4;
        const int o0 = ty * 4;
        const int q4 = tx * 4;
        float r00[4], r01[4], r02[4], r03[4];
        const float bz0 = __ldg(b3 + o0 + 0);
        const float bz1 = __ldg(b3 + o0 + 1);
        const float bz2 = __ldg(b3 + o0 + 2);
        const float bz3 = __ldg(b3 + o0 + 3);
        #pragma unroll
        for (int k = 0; k < 4; ++k) { r00[k] = bz0; r01[k] = bz1; r02[k] = bz2; r03[k] = bz3; }

        #pragma unroll 4
        for (int j = 0; j < 64; ++j) {
            const float4 wv = *reinterpret_cast<const float4*>(&s_w3[j * 68 + o0]);
            const float4 fv = *reinterpret_cast<const float4*>(&s_fin[j * 68 + q4]);
            r00[0] = fmaf(wv.x, fv.x, r00[0]); r00[1] = fmaf(wv.x, fv.y, r00[1]);
            r00[2] = fmaf(wv.x, fv.z, r00[2]); r00[3] = fmaf(wv.x, fv.w, r00[3]);
            r01[0] = fmaf(wv.y, fv.x, r01[0]); r01[1] = fmaf(wv.y, fv.y, r01[1]);
            r01[2] = fmaf(wv.y, fv.z, r01[2]); r01[3] = fmaf(wv.y, fv.w, r01[3]);
            r02[0] = fmaf(wv.z, fv.x, r02[0]); r02[1] = fmaf(wv.z, fv.y, r02[1]);
            r02[2] = fmaf(wv.z, fv.z, r02[2]); r02[3] = fmaf(wv.z, fv.w, r02[3]);
            r03[0] = fmaf(wv.w, fv.x, r03[0]); r03[1] = fmaf(wv.w, fv.y, r03[1]);
            r03[2] = fmaf(wv.w, fv.z, r03[2]); r03[3] = fmaf(wv.w, fv.w, r03[3]);
        }
        float* op = out + (size_t)(b * 64 + o0) * HW + q0 + q4;
        *reinterpret_cast<float4*>(op) =
            make_float4(fmaxf(r00[0],0.f), fmaxf(r00[1],0.f), fmaxf(r00[2],0.f), fmaxf(r00[3],0.f));
        *reinterpret_cast<float4*>(op + HW) =
            make_float4(fmaxf(r01[0],0.f), fmaxf(r01[1],0.f), fmaxf(r01[2],0.f), fmaxf(r01[3],0.f));
        *reinterpret_cast<float4*>(op + 2 * HW) =
            make_float4(fmaxf(r02[0],0.f), fmaxf(r02[1],0.f), fmaxf(r02[2],0.f), fmaxf(r02[3],0.f));
        *reinterpret_cast<float4*>(op + 3 * HW) =
            make_float4(fmaxf(r03[0],0.f), fmaxf(r03[1],0.f), fmaxf(r03[2],0.f), fmaxf(r03[3],0.f));
    }
}

// ---------------- launch ----------------
extern "C" void kernel_launch(void* const* d_in, const int* in_sizes, int n_in,
                              void* d_out, int out_size) {
    const float* uv  = (const float*)d_in[0];
    // d_in[1] = feat_2d : unused by the reference computation
    const float* f3d = (const float*)d_in[2];
    const float* w1  = (const float*)d_in[3];
    const float* b1  = (const float*)d_in[4];
    const float* w2  = (const float*)d_in[5];
    const float* b2  = (const float*)d_in[6];
    const float* w3  = (const float*)d_in[7];
    const float* b3  = (const float*)d_in[8];
    float* out = (float*)d_out;

    prep_kernel<<<1024 + 64, 256>>>(uv, f3d);
    scan_kernel<<<1, 1024>>>();
    scatter_kernel<<<64, 256>>>();
    fused_kernel<<<dim3(HW / 64, BS), 256>>>(w1, b1, w2, b2, w3, b3, out);
}

// round 8
// speedup vs baseline: 5.3412x; 1.0006x over previous
#include <cuda_runtime.h>
#include <math.h>

#define BS 2
#define NPTS 8192
#define C3D 64
#define HH 64
#define WW 160
#define HW (HH*WW)
#define KNN 3

#define CW 80          // cells in x (2px each)
#define CHC 32         // cells in y
#define NCELL (CW*CHC)
#define NTOT (BS*NCELL)

#define NCAND 576      // smem candidate cap (expected ~175, Poisson tail ~0)

#define FLT_BIG 3.402823466e+38f

// ---------------- scratch ----------------
__device__ float4 g_pts[BS * NPTS];        // (x, y, s2_replica, 0) by original index
__device__ int    g_cnt[NTOT];             // zero-init; re-zeroed by fused kernel each run
__device__ int    g_rowstart[NTOT + 1];
__device__ int    g_off[NTOT];
__device__ float4 g_cpts[BS * NPTS];       // CSR-compacted (x, y, s2, idx_bits)
__device__ float  g_f3dT[BS * NPTS * C3D]; // point-major feat_3d

__device__ __forceinline__ int cell_of(float ux, float uy, int b) {
    int cx = (int)(ux * 0.5f); cx = max(0, min(CW - 1, cx));
    int cy = (int)(uy * 0.5f); cy = max(0, min(CHC - 1, cy));
    return (b * CHC + cy) * CW + cx;
}

// ---------------- K1: transpose feat_3d (vectorized) + pack/count ----------
__global__ void __launch_bounds__(256) prep_kernel(const float* __restrict__ uv,
                                                   const float* __restrict__ f3d) {
    const int t = threadIdx.x;
    if (blockIdx.x < 1024) {
        __shared__ float tile[32][33];
        const int bid = blockIdx.x;
        const int b  = bid >> 9;
        const int c0 = ((bid >> 8) & 1) * 32;
        const int n0 = (bid & 255) * 32;
        const int tx2 = t & 7;
        const int row = t >> 3;
        float4 v = *reinterpret_cast<const float4*>(
            f3d + ((size_t)(b * C3D + c0 + row)) * NPTS + n0 + tx2 * 4);
        tile[row][tx2 * 4 + 0] = v.x;
        tile[row][tx2 * 4 + 1] = v.y;
        tile[row][tx2 * 4 + 2] = v.z;
        tile[row][tx2 * 4 + 3] = v.w;
        __syncthreads();
        const int n = t >> 3;
        float4 o;
        o.x = tile[tx2 * 4 + 0][n];
        o.y = tile[tx2 * 4 + 1][n];
        o.z = tile[tx2 * 4 + 2][n];
        o.w = tile[tx2 * 4 + 3][n];
        *reinterpret_cast<float4*>(
            g_f3dT + ((size_t)(b * NPTS + n0 + n)) * C3D + c0 + tx2 * 4) = o;
    } else {
        const int i = (blockIdx.x - 1024) * 256 + t;
        const int b = i >> 13;
        const int n = i & (NPTS - 1);
        const float ux = uv[(b * 2 + 0) * NPTS + n];
        const float uy = uv[(b * 2 + 1) * NPTS + n];
        const float s2 = __fadd_rn(__fmul_rn(ux, ux), __fmul_rn(uy, uy));
        g_pts[i] = make_float4(ux, uy, s2, 0.0f);
        atomicAdd(&g_cnt[cell_of(ux, uy, b)], 1);
    }
}

// ---------------- K2: exclusive scan over NTOT=5120 cells (one block) ----------
__global__ void __launch_bounds__(1024) scan_kernel() {
    const int t = threadIdx.x;
    int c[5], s = 0;
    #pragma unroll
    for (int k = 0; k < 5; ++k) { c[k] = g_cnt[t * 5 + k]; s += c[k]; }
    const int lane = t & 31, w = t >> 5;
    int v = s;
    #pragma unroll
    for (int o = 1; o < 32; o <<= 1) {
        int u = __shfl_up_sync(0xffffffffu, v, o);
        if (lane >= o) v += u;
    }
    __shared__ int ws[32];
    if (lane == 31) ws[w] = v;
    __syncthreads();
    if (w == 0) {
        int x = ws[lane];
        #pragma unroll
        for (int o = 1; o < 32; o <<= 1) {
            int u = __shfl_up_sync(0xffffffffu, x, o);
            if (lane >= o) x += u;
        }
        ws[lane] = x;
    }
    __syncthreads();
    int run = v - s + (w > 0 ? ws[w - 1] : 0);
    #pragma unroll
    for (int k = 0; k < 5; ++k) {
        g_rowstart[t * 5 + k] = run;
        g_off[t * 5 + k] = run;
        run += c[k];
    }
    if (t == 1023) g_rowstart[NTOT] = run;
}

// ---------------- K3: scatter into CSR ----------------
__global__ void __launch_bounds__(256) scatter_kernel() {
    const int i = blockIdx.x * 256 + threadIdx.x;
    const int b = i >> 13;
    const int n = i & (NPTS - 1);
    const float4 p = g_pts[i];
    const int slot = atomicAdd(&g_off[cell_of(p.x, p.y, b)], 1);
    g_cpts[slot] = make_float4(p.x, p.y, p.z, __int_as_float(n));
}

// ---------------- helpers ----------------
__device__ __forceinline__ bool lessMI(float ma, int ia, float mb, int ib) {
    return (ma < mb) || (ma == mb && ia < ib);
}
__device__ __forceinline__ void ins(float d, int id,
                                    float& d0, float& d1, float& d2v,
                                    int& j0, int& j1, int& j2) {
    if (lessMI(d, id, d2v, j2)) {
        if (lessMI(d, id, d1, j1)) {
            d2v = d1; j2 = j1;
            if (lessMI(d, id, d0, j0)) { d1 = d0; j1 = j0; d0 = d; j0 = id; }
            else                       { d1 = d;  j1 = id; }
        } else { d2v = d; j2 = id; }
    }
}
__device__ __forceinline__ void eval_pt(const float4 p, float qxf, float qyf, float s1,
                                        float& d0, float& d1, float& d2v,
                                        int& j0, int& j1, int& j2) {
    const float dot = __fmaf_rn(qyf, p.y, __fmul_rn(qxf, p.x));
    const float d2  = __fsub_rn(__fadd_rn(s1, p.z), __fmul_rn(2.0f, dot));
    ins(d2, __float_as_int(p.w), d0, d1, d2v, j0, j1, j2);
}
__device__ __forceinline__ void scan_span(int st, int en, int stride,
                                          float qxf, float qyf, float s1,
                                          float& d0, float& d1, float& d2v,
                                          int& j0, int& j1, int& j2) {
    for (int s = st; s < en; s += stride)
        eval_pt(__ldg(&g_cpts[s]), qxf, qyf, s1, d0, d1, d2v, j0, j1, j2);
}
__device__ __forceinline__ void row_bounds(int b, int cy, int cxlo, int cxhi,
                                           int& st, int& en) {
    st = 0; en = 0;
    if (cy < 0 || cy >= CHC) return;
    cxlo = max(cxlo, 0); cxhi = min(cxhi, CW - 1);
    if (cxlo > cxhi) return;
    const int rowbase = (b * CHC + cy) * CW;
    st = g_rowstart[rowbase + cxlo];
    en = g_rowstart[rowbase + cxhi + 1];
}

// ---------------- K4: fused knn(smem-staged) + MLP + w3 block-GEMM ----------
// block = 32x2 pixel tile (64 queries). grid (5, 32, BS).
__global__ void __launch_bounds__(256) fused_kernel(
    const float* __restrict__ w1, const float* __restrict__ b1,
    const float* __restrict__ w2, const float* __restrict__ b2,
    const float* __restrict__ w3, const float* __restrict__ b3,
    float* __restrict__ out) {

    __shared__ float  s_w3[64 * 68];   // [j*68 + o] = w3[o][j]
    __shared__ float  s_buf[64 * 68];  // union: s_H [qk*20+j] then s_fin [j*68+lq]
    __shared__ float4 s_cand[NCAND];   // staged candidate points
    __shared__ int    s_rs[3][20];     // absolute rowstart boundaries per cell-row
    __shared__ int    s_st[3], s_cnt[3];
    __shared__ int4   s_knn[64];
    __shared__ float  s_w1[48];
    __shared__ float  s_b1[16];

    float* const s_H   = s_buf;
    float* const s_fin = s_buf;

    const int t    = threadIdx.x;
    const int lane = t & 31;
    const int wib  = t >> 5;
    const int b    = blockIdx.z;
    const int X0   = blockIdx.x * 32;
    const int Y0   = blockIdx.y * 2;

    // tile's shared cell neighborhood
    const int cyc  = Y0 >> 1;
    const int cxlo = max(X0 / 2 - 1, 0);
    const int cxhi = min(X0 / 2 + 16, CW - 1);

    // reset cell counters for next invocation (consumed earlier this run by scan)
    const int gtid = ((blockIdx.z * gridDim.y + blockIdx.y) * gridDim.x + blockIdx.x) * 256 + t;
    if (gtid < NTOT) g_cnt[gtid] = 0;

    if (t < 48) s_w1[t] = w1[t];
    if (t < 16) s_b1[t] = b1[t];

    // row bounds + boundary table
    if (t < 3) {
        const int row = cyc - 1 + t;
        int st = 0, en = 0;
        if (row >= 0 && row < CHC) {
            const int rowbase = (b * CHC + row) * CW;
            st = g_rowstart[rowbase + cxlo];
            en = g_rowstart[rowbase + cxhi + 1];
        }
        s_st[t] = st; s_cnt[t] = en - st;
    }
    if (t < 60) {
        const int r = t / 20, c = t % 20;
        const int row = cyc - 1 + r;
        if (row >= 0 && row < CHC && c <= cxhi + 1 - cxlo)
            s_rs[r][c] = g_rowstart[(b * CHC + row) * CW + cxlo + c];
    }
    __syncthreads();

    const int cnt0 = s_cnt[0], cnt1 = s_cnt[1], cnt2 = s_cnt[2];
    const int base1 = cnt0, base2 = cnt0 + cnt1;
    const bool ovf = (base2 + cnt2) > NCAND;

    if (!ovf) {
        for (int i = t; i < cnt0; i += 256) s_cand[i]         = __ldg(&g_cpts[s_st[0] + i]);
        for (int i = t; i < cnt1; i += 256) s_cand[base1 + i] = __ldg(&g_cpts[s_st[1] + i]);
        for (int i = t; i < cnt2; i += 256) s_cand[base2 + i] = __ldg(&g_cpts[s_st[2] + i]);
    }

    // stage w3 transposed (coalesced gmem reads) — overlaps candidate copy
    for (int e = t; e < 64 * 64; e += 256) {
        int o = e >> 6, j = e & 63;
        s_w3[j * 68 + o] = w3[e];
    }
    __syncthreads();

    // ---- phase A: knn, 4 lanes per query, 3x3 window from smem ----
    const int sub = lane & 3;
    const int qq0 = lane >> 2;               // 0..7
    const int lq  = wib * 8 + qq0;           // 0..63
    const int qx  = X0 + (lq & 31);
    const int qy  = Y0 + (lq >> 5);
    const float qxf = (float)qx;
    const float qyf = (float)qy;
    const float s1  = __fadd_rn(__fmul_rn(qxf, qxf), __fmul_rn(qyf, qyf));
    const int qcx = qx >> 1;

    float d0 = FLT_BIG, d1 = FLT_BIG, d2v = FLT_BIG;
    int   j0 = 0x7fffffff, j1 = 0x7fffffff, j2 = 0x7fffffff;

    if (!ovf) {
        const int lo_i = max(qcx - 1, cxlo) - cxlo;
        const int hi_i = min(qcx + 1, cxhi) - cxlo;
        #pragma unroll
        for (int r = 0; r < 3; ++r) {
            const int row = cyc - 1 + r;
            if (row < 0 || row >= CHC) continue;
            const int base_r = (r == 0) ? 0 : (r == 1) ? base1 : base2;
            const int ss = s_rs[r][lo_i]     - s_st[r] + base_r;
            const int ee = s_rs[r][hi_i + 1] - s_st[r] + base_r;
            for (int s = ss + sub; s < ee; s += 4)
                eval_pt(s_cand[s], qxf, qyf, s1, d0, d1, d2v, j0, j1, j2);
        }
    } else {
        // rare overflow: identical candidate set scanned from gmem
        #pragma unroll
        for (int dy = -1; dy <= 1; ++dy) {
            int st, en;
            row_bounds(b, cyc + dy, qcx - 1, qcx + 1, st, en);
            scan_span(st + sub, en, 4, qxf, qyf, s1, d0, d1, d2v, j0, j1, j2);
        }
    }

    // merge across the 4-lane group (total order on (d2, idx) -> exact)
    #pragma unroll
    for (int m = 1; m <= 2; m <<= 1) {
        float od0 = __shfl_xor_sync(0xffffffffu, d0,  m);
        float od1 = __shfl_xor_sync(0xffffffffu, d1,  m);
        float od2 = __shfl_xor_sync(0xffffffffu, d2v, m);
        int   oj0 = __shfl_xor_sync(0xffffffffu, j0,  m);
        int   oj1 = __shfl_xor_sync(0xffffffffu, j1,  m);
        int   oj2 = __shfl_xor_sync(0xffffffffu, j2,  m);
        ins(od0, oj0, d0, d1, d2v, j0, j1, j2);
        ins(od1, oj1, d0, d1, d2v, j0, j1, j2);
        ins(od2, oj2, d0, d1, d2v, j0, j1, j2);
    }

    if (sub == 0) {
        // rare exact fallback: 3x3 guarantees >=2px coverage; trust iff d2v+0.5 < 4
        if (d2v + 0.5f >= 4.0f) {
            for (int r = 2; r < 96; ++r) {
                const float lb = 2.0f * (float)(r - 1);
                if (lb * lb > d2v + 0.5f) break;
                int st, en;
                row_bounds(b, cyc - r, qcx - r, qcx + r, st, en);
                scan_span(st, en, 1, qxf, qyf, s1, d0, d1, d2v, j0, j1, j2);
                row_bounds(b, cyc + r, qcx - r, qcx + r, st, en);
                scan_span(st, en, 1, qxf, qyf, s1, d0, d1, d2v, j0, j1, j2);
                for (int dy = -r + 1; dy <= r - 1; ++dy) {
                    row_bounds(b, cyc + dy, qcx - r, qcx - r, st, en);
                    scan_span(st, en, 1, qxf, qyf, s1, d0, d1, d2v, j0, j1, j2);
                    row_bounds(b, cyc + dy, qcx + r, qcx + r, st, en);
                    scan_span(st, en, 1, qxf, qyf, s1, d0, d1, d2v, j0, j1, j2);
                }
            }
        }
        s_knn[lq] = make_int4(j0, j1, j2, 0);
    }
    __syncthreads();

    // ---- phase B1: hidden layer, one thread per (query,k) pair ----
    if (t < 192) {
        const int blq = t / 3;
        const int k   = t - blq * 3;
        const int4 kn = s_knn[blq];
        const int idx = (k == 0) ? kn.x : (k == 1) ? kn.y : kn.z;
        const float4 p = __ldg(&g_pts[b * NPTS + idx]);
        const float mqx = (float)(X0 + (blq & 31));
        const float mqy = (float)(Y0 + (blq >> 5));
        const float ox = p.x - mqx;
        const float oy = p.y - mqy;
        const float nr = sqrtf(ox * ox + oy * oy);
        #pragma unroll
        for (int j = 0; j < 16; j += 4) {
            float4 hv;
            hv.x = fmaxf(fmaf(s_w1[(j+0)*3], ox, fmaf(s_w1[(j+0)*3+1], oy, fmaf(s_w1[(j+0)*3+2], nr, s_b1[j+0]))), 0.f);
            hv.y = fmaxf(fmaf(s_w1[(j+1)*3], ox, fmaf(s_w1[(j+1)*3+1], oy, fmaf(s_w1[(j+1)*3+2], nr, s_b1[j+1]))), 0.f);
            hv.z = fmaxf(fmaf(s_w1[(j+2)*3], ox, fmaf(s_w1[(j+2)*3+1], oy, fmaf(s_w1[(j+2)*3+2], nr, s_b1[j+2]))), 0.f);
            hv.w = fmaxf(fmaf(s_w1[(j+3)*3], ox, fmaf(s_w1[(j+3)*3+1], oy, fmaf(s_w1[(j+3)*3+2], nr, s_b1[j+3]))), 0.f);
            *reinterpret_cast<float4*>(&s_H[t * 20 + j]) = hv;
        }
    }

    float w2r0[16], w2r1[16];
    #pragma unroll
    for (int j = 0; j < 16; ++j) {
        w2r0[j] = w2[lane * 16 + j];
        w2r1[j] = w2[(lane + 32) * 16 + j];
    }
    const float b2a = b2[lane], b2b = b2[lane + 32];
    __syncthreads();

    // ---- phase B2: score + gather (warp = 8 queries, lane = 2 channels) ----
    float acc0q[8], acc1q[8];
    #pragma unroll
    for (int qq = 0; qq < 8; ++qq) {
        const int blq = wib * 8 + qq;
        const int4 kn = s_knn[blq];
        float a0 = 0.f, a1 = 0.f;
        #pragma unroll
        for (int k = 0; k < KNN; ++k) {
            const int idx = (k == 0) ? kn.x : (k == 1) ? kn.y : kn.z;
            const float* hp = &s_H[(blq * 3 + k) * 20];
            const float4 h0 = *reinterpret_cast<const float4*>(hp);
            const float4 h1 = *reinterpret_cast<const float4*>(hp + 4);
            const float4 h2 = *reinterpret_cast<const float4*>(hp + 8);
            const float4 h3 = *reinterpret_cast<const float4*>(hp + 12);
            float e0 = b2a, e1 = b2b;
            e0 = fmaf(w2r0[0],  h0.x, e0); e1 = fmaf(w2r1[0],  h0.x, e1);
            e0 = fmaf(w2r0[1],  h0.y, e0); e1 = fmaf(w2r1[1],  h0.y, e1);
            e0 = fmaf(w2r0[2],  h0.z, e0); e1 = fmaf(w2r1[2],  h0.z, e1);
            e0 = fmaf(w2r0[3],  h0.w, e0); e1 = fmaf(w2r1[3],  h0.w, e1);
            e0 = fmaf(w2r0[4],  h1.x, e0); e1 = fmaf(w2r1[4],  h1.x, e1);
            e0 = fmaf(w2r0[5],  h1.y, e0); e1 = fmaf(w2r1[5],  h1.y, e1);
            e0 = fmaf(w2r0[6],  h1.z, e0); e1 = fmaf(w2r1[6],  h1.z, e1);
            e0 = fmaf(w2r0[7],  h1.w, e0); e1 = fmaf(w2r1[7],  h1.w, e1);
            e0 = fmaf(w2r0[8],  h2.x, e0); e1 = fmaf(w2r1[8],  h2.x, e1);
            e0 = fmaf(w2r0[9],  h2.y, e0); e1 = fmaf(w2r1[9],  h2.y, e1);
            e0 = fmaf(w2r0[10], h2.z, e0); e1 = fmaf(w2r1[10], h2.z, e1);
            e0 = fmaf(w2r0[11], h2.w, e0); e1 = fmaf(w2r1[11], h2.w, e1);
            e0 = fmaf(w2r0[12], h3.x, e0); e1 = fmaf(w2r1[12], h3.x, e1);
            e0 = fmaf(w2r0[13], h3.y, e0); e1 = fmaf(w2r1[13], h3.y, e1);
            e0 = fmaf(w2r0[14], h3.z, e0); e1 = fmaf(w2r1[14], h3.z, e1);
            e0 = fmaf(w2r0[15], h3.w, e0); e1 = fmaf(w2r1[15], h3.w, e1);
            const float s0  = 1.f / (1.f + __expf(-e0));
            const float s1v = 1.f / (1.f + __expf(-e1));
            const float* fp = g_f3dT + (size_t)(b * NPTS + idx) * C3D;
            a0 = fmaf(s0,  __ldg(fp + lane),      a0);
            a1 = fmaf(s1v, __ldg(fp + lane + 32), a1);
        }
        acc0q[qq] = a0;
        acc1q[qq] = a1;
    }
    __syncthreads();   // all reads of s_H complete before aliased s_fin writes

    {
        float* r0 = &s_fin[lane * 68 + wib * 8];
        float* r1 = &s_fin[(lane + 32) * 68 + wib * 8];
        *reinterpret_cast<float4*>(r0)     = make_float4(acc0q[0], acc0q[1], acc0q[2], acc0q[3]);
        *reinterpret_cast<float4*>(r0 + 4) = make_float4(acc0q[4], acc0q[5], acc0q[6], acc0q[7]);
        *reinterpret_cast<float4*>(r1)     = make_float4(acc1q[0], acc1q[1], acc1q[2], acc1q[3]);
        *reinterpret_cast<float4*>(r1 + 4) = make_float4(acc1q[4], acc1q[5], acc1q[6], acc1q[7]);
    }
    __syncthreads();

    // ---- phase C: w3 block GEMM, 4x4 register tile per thread ----
    {
        const int tx_ = t & 15;
        const int ty_ = t >> 4;
        const int o0 = ty_ * 4;
        const int q4 = tx_ * 4;            // stays within one 32-query row
        float r00[4], r01[4], r02[4], r03[4];
        const float bz0 = __ldg(b3 + o0 + 0);
        const float bz1 = __ldg(b3 + o0 + 1);
        const float bz2 = __ldg(b3 + o0 + 2);
        const float bz3 = __ldg(b3 + o0 + 3);
        #pragma unroll
        for (int k = 0; k < 4; ++k) { r00[k] = bz0; r01[k] = bz1; r02[k] = bz2; r03[k] = bz3; }

        #pragma unroll 4
        for (int j = 0; j < 64; ++j) {
            const float4 wv = *reinterpret_cast<const float4*>(&s_w3[j * 68 + o0]);
            const float4 fv = *reinterpret_cast<const float4*>(&s_fin[j * 68 + q4]);
            r00[0] = fmaf(wv.x, fv.x, r00[0]); r00[1] = fmaf(wv.x, fv.y, r00[1]);
            r00[2] = fmaf(wv.x, fv.z, r00[2]); r00[3] = fmaf(wv.x, fv.w, r00[3]);
            r01[0] = fmaf(wv.y, fv.x, r01[0]); r01[1] = fmaf(wv.y, fv.y, r01[1]);
            r01[2] = fmaf(wv.y, fv.z, r01[2]); r01[3] = fmaf(wv.y, fv.w, r01[3]);
            r02[0] = fmaf(wv.z, fv.x, r02[0]); r02[1] = fmaf(wv.z, fv.y, r02[1]);
            r02[2] = fmaf(wv.z, fv.z, r02[2]); r02[3] = fmaf(wv.z, fv.w, r02[3]);
            r03[0] = fmaf(wv.w, fv.x, r03[0]); r03[1] = fmaf(wv.w, fv.y, r03[1]);
            r03[2] = fmaf(wv.w, fv.z, r03[2]); r03[3] = fmaf(wv.w, fv.w, r03[3]);
        }
        const int qy_row = Y0 + (q4 >> 5);
        const int qx0    = X0 + (q4 & 31);
        float* op = out + (size_t)(b * 64 + o0) * HW + qy_row * WW + qx0;
        *reinterpret_cast<float4*>(op) =
            make_float4(fmaxf(r00[0],0.f), fmaxf(r00[1],0.f), fmaxf(r00[2],0.f), fmaxf(r00[3],0.f));
        *reinterpret_cast<float4*>(op + HW) =
            make_float4(fmaxf(r01[0],0.f), fmaxf(r01[1],0.f), fmaxf(r01[2],0.f), fmaxf(r01[3],0.f));
        *reinterpret_cast<float4*>(op + 2 * HW) =
            make_float4(fmaxf(r02[0],0.f), fmaxf(r02[1],0.f), fmaxf(r02[2],0.f), fmaxf(r02[3],0.f));
        *reinterpret_cast<float4*>(op + 3 * HW) =
            make_float4(fmaxf(r03[0],0.f), fmaxf(r03[1],0.f), fmaxf(r03[2],0.f), fmaxf(r03[3],0.f));
    }
}

// ---------------- launch ----------------
extern "C" void kernel_launch(void* const* d_in, const int* in_sizes, int n_in,
                              void* d_out, int out_size) {
    const float* uv  = (const float*)d_in[0];
    // d_in[1] = feat_2d : unused by the reference computation
    const float* f3d = (const float*)d_in[2];
    const float* w1  = (const float*)d_in[3];
    const float* b1  = (const float*)d_in[4];
    const float* w2  = (const float*)d_in[5];
    const float* b2  = (const float*)d_in[6];
    const float* w3  = (const float*)d_in[7];
    const float* b3  = (const float*)d_in[8];
    float* out = (float*)d_out;

    prep_kernel<<<1024 + 64, 256>>>(uv, f3d);
    scan_kernel<<<1, 1024>>>();
    scatter_kernel<<<64, 256>>>();
    fused_kernel<<<dim3(WW / 32, HH / 2, BS), 256>>>(w1, b1, w2, b2, w3, b3, out);
}